// round 4
// baseline (speedup 1.0000x reference)
#include <cuda_runtime.h>
#include <math.h>

#define H      256
#define NB     512      // n_graphs
#define G4     1024     // 4*H
#define K2H    512      // 2*H

// ---------------- device scratch (no allocation allowed) ----------------
__device__ float g_Wc[G4 * K2H];     // combined gate weight [1024][512]
__device__ float g_bias[G4];         // b_ih + b_hh
__device__ float g_hs[NB * H];
__device__ float g_cs[NB * H];
__device__ float g_qstar[NB * K2H];  // [hs, r]
__device__ float g_gates[NB * G4];
__device__ int   g_seg[NB + 1];

// ---------------- weight prep: Wcomb = [W_ih[:, :H] + W_hh | W_ih[:, H:]] ----------------
__global__ void prep_kernel(const float* __restrict__ W_ih, const float* __restrict__ W_hh,
                            const float* __restrict__ b_ih, const float* __restrict__ b_hh) {
    int i = blockIdx.x * blockDim.x + threadIdx.x;
    if (i < G4 * K2H) {
        int j = i >> 9;      // row (gate index)
        int k = i & 511;     // col
        float v = W_ih[i];
        if (k < H) v += W_hh[j * H + k];
        g_Wc[i] = v;
    }
    if (i < G4) g_bias[i] = b_ih[i] + b_hh[i];
}

// ---------------- segment starts via binary search (batch is sorted) ----------------
// dtype-agnostic: batch may be int32 or int64. If int64, the int32 view's last
// word is the high half of the last element (values < 512 -> 0). If int32, the
// last word is the max graph id (~511, nonzero).
__global__ void seg_kernel(const void* __restrict__ batch_raw, int n) {
    int g = blockIdx.x * blockDim.x + threadIdx.x;
    if (g > NB) return;
    const int* b32 = (const int*)batch_raw;
    bool is64 = (b32[n - 1] == 0);
    int lo = 0, hi = n;
    if (is64) {
        const long long* b64 = (const long long*)batch_raw;
        long long gv = (long long)g;
        while (lo < hi) { int mid = (lo + hi) >> 1; if (b64[mid] < gv) lo = mid + 1; else hi = mid; }
    } else {
        while (lo < hi) { int mid = (lo + hi) >> 1; if (b32[mid] < g) lo = mid + 1; else hi = mid; }
    }
    g_seg[g] = lo;   // lower_bound(g); g==NB gives n
}

__device__ __forceinline__ float sigf(float v) { return 1.0f / (1.0f + __expf(-v)); }

// ---------------- LSTM step 1: q_star = hs = 0 -> gates = bias only ----------------
__global__ void lstm_first() {
    int idx = blockIdx.x * blockDim.x + threadIdx.x;   // NB*H
    int t = idx & (H - 1);
    float ig = g_bias[t], gg = g_bias[2 * H + t], og = g_bias[3 * H + t];
    float c = sigf(ig) * tanhf(gg);        // f-gate * cs(=0) drops out
    float h = sigf(og) * tanhf(c);
    g_cs[idx] = c;
    g_hs[idx] = h;
}

// ---------------- LSTM steps 2..: consume g_gates ----------------
__global__ void lstm_step() {
    int idx = blockIdx.x * blockDim.x + threadIdx.x;   // NB*H
    int g = idx >> 8;
    int t = idx & (H - 1);
    const float* gr = g_gates + g * G4;
    float ig = gr[t], fg = gr[H + t], gg = gr[2 * H + t], og = gr[3 * H + t];
    float c = sigf(fg) * g_cs[idx] + sigf(ig) * tanhf(gg);
    float h = sigf(og) * tanhf(c);
    g_cs[idx] = c;
    g_hs[idx] = h;
}

// ---------------- fused attention: one pass over x per step (online softmax) ----------------
// One block per graph (contiguous node range). 8 warps stride nodes; each lane
// owns 8 of the 256 hidden dims. Per node: 2x LDG.128, warp-reduce dot, online
// softmax update of (m, d, r[8]). Warps merged at the end via smem.
__global__ __launch_bounds__(256) void attn_kernel(const float* __restrict__ x) {
    int g = blockIdx.x;
    int start = g_seg[g], end = g_seg[g + 1];
    int warp = threadIdx.x >> 5, lane = threadIdx.x & 31;

    const float4* qv = reinterpret_cast<const float4*>(g_hs + g * H);
    float4 q0 = qv[lane * 2];
    float4 q1 = qv[lane * 2 + 1];

    float m = -3.0e38f;   // finite "-inf" avoids inf-inf NaN paths
    float d = 0.0f;
    float r0 = 0.f, r1 = 0.f, r2 = 0.f, r3 = 0.f, r4 = 0.f, r5 = 0.f, r6 = 0.f, r7 = 0.f;

    for (int nidx = start + warp; nidx < end; nidx += 8) {
        const float4* xv = reinterpret_cast<const float4*>(x + (size_t)nidx * H);
        float4 a = xv[lane * 2];
        float4 b = xv[lane * 2 + 1];
        float p = a.x * q0.x + a.y * q0.y + a.z * q0.z + a.w * q0.w
                + b.x * q1.x + b.y * q1.y + b.z * q1.z + b.w * q1.w;
        #pragma unroll
        for (int o = 16; o > 0; o >>= 1) p += __shfl_xor_sync(0xffffffffu, p, o);

        if (p > m) {
            float f = __expf(m - p);
            d *= f;
            r0 *= f; r1 *= f; r2 *= f; r3 *= f; r4 *= f; r5 *= f; r6 *= f; r7 *= f;
            m = p;
        }
        float w = __expf(p - m);
        d += w;
        r0 = fmaf(w, a.x, r0); r1 = fmaf(w, a.y, r1);
        r2 = fmaf(w, a.z, r2); r3 = fmaf(w, a.w, r3);
        r4 = fmaf(w, b.x, r4); r5 = fmaf(w, b.y, r5);
        r6 = fmaf(w, b.z, r6); r7 = fmaf(w, b.w, r7);
    }

    __shared__ float sm_m[8], sm_d[8];
    __shared__ float sm_r[8][H];
    if (lane == 0) { sm_m[warp] = m; sm_d[warp] = d; }
    __syncthreads();

    float M = sm_m[0];
    #pragma unroll
    for (int w = 1; w < 8; w++) M = fmaxf(M, sm_m[w]);
    float D = 0.f;
    #pragma unroll
    for (int w = 0; w < 8; w++) D += sm_d[w] * __expf(sm_m[w] - M);

    float sc = __expf(m - M);
    int base = lane * 8;
    sm_r[warp][base + 0] = r0 * sc; sm_r[warp][base + 1] = r1 * sc;
    sm_r[warp][base + 2] = r2 * sc; sm_r[warp][base + 3] = r3 * sc;
    sm_r[warp][base + 4] = r4 * sc; sm_r[warp][base + 5] = r5 * sc;
    sm_r[warp][base + 6] = r6 * sc; sm_r[warp][base + 7] = r7 * sc;
    __syncthreads();

    int t = threadIdx.x;
    float R = 0.f;
    #pragma unroll
    for (int w = 0; w < 8; w++) R += sm_r[w][t];
    R = (D > 0.f) ? (R / D) : 0.f;

    g_qstar[g * K2H + t]     = g_hs[g * H + t];   // q half
    g_qstar[g * K2H + H + t] = R;                 // r half
}

// ---------------- tiled fp32 NT GEMM: C[M][N] = A[M][K] @ B[N][K]^T + bias[N] ----------------
#define BM 64
#define BN 64
#define BKK 16

__device__ __forceinline__ void gemm_nt_body(const float* __restrict__ A,
                                             const float* __restrict__ Bm,
                                             const float* __restrict__ bias,
                                             float* __restrict__ C,
                                             int Ndim, int Kdim) {
    __shared__ float sA[BKK][BM + 1];
    __shared__ float sB[BKK][BN + 1];
    int tid = threadIdx.x;
    int tx = tid & 15, ty = tid >> 4;
    int row0 = blockIdx.y * BM, col0 = blockIdx.x * BN;
    float acc[4][4] = {};

    for (int k0 = 0; k0 < Kdim; k0 += BKK) {
        #pragma unroll
        for (int i = 0; i < 4; i++) {
            int li = tid + i * 256;           // 0..1023
            int r = li >> 4, c = li & 15;
            sA[c][r] = A[(size_t)(row0 + r) * Kdim + k0 + c];
            sB[c][r] = Bm[(size_t)(col0 + r) * Kdim + k0 + c];
        }
        __syncthreads();
        #pragma unroll
        for (int kk = 0; kk < BKK; kk++) {
            float a0 = sA[kk][ty * 4 + 0], a1 = sA[kk][ty * 4 + 1];
            float a2 = sA[kk][ty * 4 + 2], a3 = sA[kk][ty * 4 + 3];
            float b0 = sB[kk][tx * 4 + 0], b1 = sB[kk][tx * 4 + 1];
            float b2 = sB[kk][tx * 4 + 2], b3 = sB[kk][tx * 4 + 3];
            acc[0][0] = fmaf(a0, b0, acc[0][0]); acc[0][1] = fmaf(a0, b1, acc[0][1]);
            acc[0][2] = fmaf(a0, b2, acc[0][2]); acc[0][3] = fmaf(a0, b3, acc[0][3]);
            acc[1][0] = fmaf(a1, b0, acc[1][0]); acc[1][1] = fmaf(a1, b1, acc[1][1]);
            acc[1][2] = fmaf(a1, b2, acc[1][2]); acc[1][3] = fmaf(a1, b3, acc[1][3]);
            acc[2][0] = fmaf(a2, b0, acc[2][0]); acc[2][1] = fmaf(a2, b1, acc[2][1]);
            acc[2][2] = fmaf(a2, b2, acc[2][2]); acc[2][3] = fmaf(a2, b3, acc[2][3]);
            acc[3][0] = fmaf(a3, b0, acc[3][0]); acc[3][1] = fmaf(a3, b1, acc[3][1]);
            acc[3][2] = fmaf(a3, b2, acc[3][2]); acc[3][3] = fmaf(a3, b3, acc[3][3]);
        }
        __syncthreads();
    }
    #pragma unroll
    for (int i = 0; i < 4; i++) {
        int rr = row0 + ty * 4 + i;
        #pragma unroll
        for (int j = 0; j < 4; j++) {
            int cc = col0 + tx * 4 + j;
            C[(size_t)rr * Ndim + cc] = acc[i][j] + bias[cc];
        }
    }
}

__global__ __launch_bounds__(256) void gemm_gates() {
    // gates[512][1024] = q_star[512][512] @ Wcomb[1024][512]^T + bias
    gemm_nt_body(g_qstar, g_Wc, g_bias, g_gates, G4, K2H);
}

__global__ __launch_bounds__(256) void gemm_out(const float* __restrict__ W_out,
                                                const float* __restrict__ b_out,
                                                float* __restrict__ out) {
    // out[512][256] = q_star[512][512] @ W_out[256][512]^T + b_out
    gemm_nt_body(g_qstar, W_out, b_out, out, H, K2H);
}

// ---------------- launcher ----------------
extern "C" void kernel_launch(void* const* d_in, const int* in_sizes, int n_in,
                              void* d_out, int out_size) {
    const float* x     = (const float*)d_in[0];
    const void*  batch = d_in[1];
    const float* W_ih  = (const float*)d_in[2];
    const float* W_hh  = (const float*)d_in[3];
    const float* b_ih  = (const float*)d_in[4];
    const float* b_hh  = (const float*)d_in[5];
    const float* W_out = (const float*)d_in[6];
    const float* b_out = (const float*)d_in[7];
    float* out = (float*)d_out;
    int n = in_sizes[0] / H;

    prep_kernel<<<(G4 * K2H + 255) / 256, 256>>>(W_ih, W_hh, b_ih, b_hh);
    seg_kernel<<<3, 256>>>(batch, n);

    // step 1: gates = bias (q_star = hs = 0)
    lstm_first<<<NB, 256>>>();
    attn_kernel<<<NB, 256>>>(x);

    // steps 2..3
    for (int s = 1; s < 3; s++) {
        gemm_gates<<<dim3(G4 / BN, NB / BM), 256>>>();
        lstm_step<<<NB, 256>>>();
        attn_kernel<<<NB, 256>>>(x);
    }

    gemm_out<<<dim3(H / BN, NB / BM), 256>>>(W_out, b_out, out);
}

// round 5
// speedup vs baseline: 1.0833x; 1.0833x over previous
#include <cuda_runtime.h>
#include <math.h>

#define H      256
#define NB     512      // n_graphs
#define G4     1024     // 4*H
#define K2H    512      // 2*H

// ---------------- device scratch (no allocation allowed) ----------------
__device__ float g_Wc[G4 * K2H];     // combined gate weight [1024][512]
__device__ float g_bias[G4];         // b_ih + b_hh
__device__ float g_hs[NB * H];
__device__ float g_cs[NB * H];
__device__ float g_qstar[NB * K2H];  // [hs, r]
__device__ float g_gates[NB * G4];
__device__ int   g_seg[NB + 1];

// ---------------- weight prep: Wcomb = [W_ih[:, :H] + W_hh | W_ih[:, H:]] ----------------
__global__ void prep_kernel(const float* __restrict__ W_ih, const float* __restrict__ W_hh,
                            const float* __restrict__ b_ih, const float* __restrict__ b_hh) {
    int i = blockIdx.x * blockDim.x + threadIdx.x;
    if (i < G4 * K2H) {
        int j = i >> 9;      // row (gate index)
        int k = i & 511;     // col
        float v = W_ih[i];
        if (k < H) v += W_hh[j * H + k];
        g_Wc[i] = v;
    }
    if (i < G4) g_bias[i] = b_ih[i] + b_hh[i];
}

// ---------------- segment starts via binary search (batch is sorted) ----------------
__global__ void seg_kernel(const void* __restrict__ batch_raw, int n) {
    int g = blockIdx.x * blockDim.x + threadIdx.x;
    if (g > NB) return;
    const int* b32 = (const int*)batch_raw;
    bool is64 = (b32[n - 1] == 0);   // int64 view: high word of last elem (values < 512)
    int lo = 0, hi = n;
    if (is64) {
        const long long* b64 = (const long long*)batch_raw;
        long long gv = (long long)g;
        while (lo < hi) { int mid = (lo + hi) >> 1; if (b64[mid] < gv) lo = mid + 1; else hi = mid; }
    } else {
        while (lo < hi) { int mid = (lo + hi) >> 1; if (b32[mid] < g) lo = mid + 1; else hi = mid; }
    }
    g_seg[g] = lo;   // lower_bound(g); g==NB gives n
}

__device__ __forceinline__ float sigf(float v) { return 1.0f / (1.0f + __expf(-v)); }

// ---------------- LSTM step 1: q_star = hs = 0 -> gates = bias only ----------------
__global__ void lstm_first() {
    int idx = blockIdx.x * blockDim.x + threadIdx.x;   // NB*H
    int t = idx & (H - 1);
    float ig = g_bias[t], gg = g_bias[2 * H + t], og = g_bias[3 * H + t];
    float c = sigf(ig) * tanhf(gg);        // f-gate * cs(=0) drops out
    float h = sigf(og) * tanhf(c);
    g_cs[idx] = c;
    g_hs[idx] = h;
}

// ---------------- LSTM steps 2..: consume g_gates ----------------
__global__ void lstm_step() {
    int idx = blockIdx.x * blockDim.x + threadIdx.x;   // NB*H
    int g = idx >> 8;
    int t = idx & (H - 1);
    const float* gr = g_gates + g * G4;
    float ig = gr[t], fg = gr[H + t], gg = gr[2 * H + t], og = gr[3 * H + t];
    float c = sigf(fg) * g_cs[idx] + sigf(ig) * tanhf(gg);
    float h = sigf(og) * tanhf(c);
    g_cs[idx] = c;
    g_hs[idx] = h;
}

// ---------------- fused attention: one pass over x per step (online softmax) ----------------
// One block (512 thr, 16 warps) per graph (contiguous node range). Each warp
// processes 2 nodes per iteration (4 independent LDG.128 up front -> high MLP,
// two interleaved shuffle-reduce chains). Each lane owns 8 of 256 hidden dims.
__global__ __launch_bounds__(512, 2) void attn_kernel(const float* __restrict__ x) {
    int g = blockIdx.x;
    int start = g_seg[g], end = g_seg[g + 1];
    int warp = threadIdx.x >> 5, lane = threadIdx.x & 31;

    const float4* qv = reinterpret_cast<const float4*>(g_hs + g * H);
    float4 q0 = qv[lane * 2];
    float4 q1 = qv[lane * 2 + 1];

    float m = -3.0e38f;   // finite "-inf" avoids inf-inf NaN paths
    float d = 0.0f;
    float r0 = 0.f, r1 = 0.f, r2 = 0.f, r3 = 0.f, r4 = 0.f, r5 = 0.f, r6 = 0.f, r7 = 0.f;

    int i = start + warp * 2;
    for (; i + 1 < end; i += 32) {
        const float4* xv0 = reinterpret_cast<const float4*>(x + (size_t)i * H);
        const float4* xv1 = reinterpret_cast<const float4*>(x + (size_t)(i + 1) * H);
        float4 a0 = xv0[lane * 2];
        float4 b0 = xv0[lane * 2 + 1];
        float4 a1 = xv1[lane * 2];
        float4 b1 = xv1[lane * 2 + 1];

        float p0 = a0.x * q0.x + a0.y * q0.y + a0.z * q0.z + a0.w * q0.w
                 + b0.x * q1.x + b0.y * q1.y + b0.z * q1.z + b0.w * q1.w;
        float p1 = a1.x * q0.x + a1.y * q0.y + a1.z * q0.z + a1.w * q0.w
                 + b1.x * q1.x + b1.y * q1.y + b1.z * q1.z + b1.w * q1.w;
        #pragma unroll
        for (int o = 16; o > 0; o >>= 1) {
            p0 += __shfl_xor_sync(0xffffffffu, p0, o);
            p1 += __shfl_xor_sync(0xffffffffu, p1, o);
        }

        // node i
        if (p0 > m) {
            float f = __expf(m - p0);
            d *= f;
            r0 *= f; r1 *= f; r2 *= f; r3 *= f; r4 *= f; r5 *= f; r6 *= f; r7 *= f;
            m = p0;
        }
        float w = __expf(p0 - m);
        d += w;
        r0 = fmaf(w, a0.x, r0); r1 = fmaf(w, a0.y, r1);
        r2 = fmaf(w, a0.z, r2); r3 = fmaf(w, a0.w, r3);
        r4 = fmaf(w, b0.x, r4); r5 = fmaf(w, b0.y, r5);
        r6 = fmaf(w, b0.z, r6); r7 = fmaf(w, b0.w, r7);

        // node i+1
        if (p1 > m) {
            float f = __expf(m - p1);
            d *= f;
            r0 *= f; r1 *= f; r2 *= f; r3 *= f; r4 *= f; r5 *= f; r6 *= f; r7 *= f;
            m = p1;
        }
        w = __expf(p1 - m);
        d += w;
        r0 = fmaf(w, a1.x, r0); r1 = fmaf(w, a1.y, r1);
        r2 = fmaf(w, a1.z, r2); r3 = fmaf(w, a1.w, r3);
        r4 = fmaf(w, b1.x, r4); r5 = fmaf(w, b1.y, r5);
        r6 = fmaf(w, b1.z, r6); r7 = fmaf(w, b1.w, r7);
    }
    if (i < end) {   // single leftover node for this warp
        const float4* xv0 = reinterpret_cast<const float4*>(x + (size_t)i * H);
        float4 a0 = xv0[lane * 2];
        float4 b0 = xv0[lane * 2 + 1];
        float p0 = a0.x * q0.x + a0.y * q0.y + a0.z * q0.z + a0.w * q0.w
                 + b0.x * q1.x + b0.y * q1.y + b0.z * q1.z + b0.w * q1.w;
        #pragma unroll
        for (int o = 16; o > 0; o >>= 1) p0 += __shfl_xor_sync(0xffffffffu, p0, o);
        if (p0 > m) {
            float f = __expf(m - p0);
            d *= f;
            r0 *= f; r1 *= f; r2 *= f; r3 *= f; r4 *= f; r5 *= f; r6 *= f; r7 *= f;
            m = p0;
        }
        float w = __expf(p0 - m);
        d += w;
        r0 = fmaf(w, a0.x, r0); r1 = fmaf(w, a0.y, r1);
        r2 = fmaf(w, a0.z, r2); r3 = fmaf(w, a0.w, r3);
        r4 = fmaf(w, b0.x, r4); r5 = fmaf(w, b0.y, r5);
        r6 = fmaf(w, b0.z, r6); r7 = fmaf(w, b0.w, r7);
    }

    __shared__ float sm_m[16], sm_d[16];
    __shared__ float sm_r[16][H];
    if (lane == 0) { sm_m[warp] = m; sm_d[warp] = d; }
    __syncthreads();

    float M = sm_m[0];
    #pragma unroll
    for (int w = 1; w < 16; w++) M = fmaxf(M, sm_m[w]);
    float D = 0.f;
    #pragma unroll
    for (int w = 0; w < 16; w++) D += sm_d[w] * __expf(sm_m[w] - M);

    float sc = __expf(m - M);   // 0 for empty warps (m=-3e38)
    int base = lane * 8;
    sm_r[warp][base + 0] = r0 * sc; sm_r[warp][base + 1] = r1 * sc;
    sm_r[warp][base + 2] = r2 * sc; sm_r[warp][base + 3] = r3 * sc;
    sm_r[warp][base + 4] = r4 * sc; sm_r[warp][base + 5] = r5 * sc;
    sm_r[warp][base + 6] = r6 * sc; sm_r[warp][base + 7] = r7 * sc;
    __syncthreads();

    int t = threadIdx.x;
    if (t < H) {
        float R = 0.f;
        #pragma unroll
        for (int w = 0; w < 16; w++) R += sm_r[w][t];
        R = (D > 0.f) ? (R / D) : 0.f;
        g_qstar[g * K2H + t]     = g_hs[g * H + t];   // q half
        g_qstar[g * K2H + H + t] = R;                 // r half
    }
}

// ---------------- tiled fp32 NT GEMM with register-prefetch double buffering ----
// C[M][N] = A[M][K] @ B[N][K]^T + bias[N]
#define BM 64
#define BN 64
#define BKK 16

__device__ __forceinline__ void gemm_nt_body(const float* __restrict__ A,
                                             const float* __restrict__ Bm,
                                             const float* __restrict__ bias,
                                             float* __restrict__ C,
                                             int Ndim, int Kdim) {
    __shared__ float sA[BKK][BM + 1];
    __shared__ float sB[BKK][BN + 1];
    int tid = threadIdx.x;
    int tx = tid & 15, ty = tid >> 4;
    int row0 = blockIdx.y * BM, col0 = blockIdx.x * BN;
    float acc[4][4] = {};

    // each thread owns 4 (r,c) slots in the 64x16 tile
    int rr[4], cc[4];
    #pragma unroll
    for (int i = 0; i < 4; i++) {
        int li = tid + i * 256;
        rr[i] = li >> 4; cc[i] = li & 15;
    }

    // prefetch k-chunk 0 into registers
    float pa[4], pb[4];
    #pragma unroll
    for (int i = 0; i < 4; i++) {
        pa[i] = A[(size_t)(row0 + rr[i]) * Kdim + cc[i]];
        pb[i] = Bm[(size_t)(col0 + rr[i]) * Kdim + cc[i]];
    }

    for (int k0 = 0; k0 < Kdim; k0 += BKK) {
        #pragma unroll
        for (int i = 0; i < 4; i++) {
            sA[cc[i]][rr[i]] = pa[i];
            sB[cc[i]][rr[i]] = pb[i];
        }
        __syncthreads();

        // issue next chunk's global loads before compute (latency overlap)
        if (k0 + BKK < Kdim) {
            #pragma unroll
            for (int i = 0; i < 4; i++) {
                pa[i] = A[(size_t)(row0 + rr[i]) * Kdim + k0 + BKK + cc[i]];
                pb[i] = Bm[(size_t)(col0 + rr[i]) * Kdim + k0 + BKK + cc[i]];
            }
        }

        #pragma unroll
        for (int kk = 0; kk < BKK; kk++) {
            float a0 = sA[kk][ty * 4 + 0], a1 = sA[kk][ty * 4 + 1];
            float a2 = sA[kk][ty * 4 + 2], a3 = sA[kk][ty * 4 + 3];
            float b0 = sB[kk][tx * 4 + 0], b1 = sB[kk][tx * 4 + 1];
            float b2 = sB[kk][tx * 4 + 2], b3 = sB[kk][tx * 4 + 3];
            acc[0][0] = fmaf(a0, b0, acc[0][0]); acc[0][1] = fmaf(a0, b1, acc[0][1]);
            acc[0][2] = fmaf(a0, b2, acc[0][2]); acc[0][3] = fmaf(a0, b3, acc[0][3]);
            acc[1][0] = fmaf(a1, b0, acc[1][0]); acc[1][1] = fmaf(a1, b1, acc[1][1]);
            acc[1][2] = fmaf(a1, b2, acc[1][2]); acc[1][3] = fmaf(a1, b3, acc[1][3]);
            acc[2][0] = fmaf(a2, b0, acc[2][0]); acc[2][1] = fmaf(a2, b1, acc[2][1]);
            acc[2][2] = fmaf(a2, b2, acc[2][2]); acc[2][3] = fmaf(a2, b3, acc[2][3]);
            acc[3][0] = fmaf(a3, b0, acc[3][0]); acc[3][1] = fmaf(a3, b1, acc[3][1]);
            acc[3][2] = fmaf(a3, b2, acc[3][2]); acc[3][3] = fmaf(a3, b3, acc[3][3]);
        }
        __syncthreads();
    }
    #pragma unroll
    for (int i = 0; i < 4; i++) {
        int orow = row0 + ty * 4 + i;
        #pragma unroll
        for (int j = 0; j < 4; j++) {
            int ocol = col0 + tx * 4 + j;
            C[(size_t)orow * Ndim + ocol] = acc[i][j] + bias[ocol];
        }
    }
}

__global__ __launch_bounds__(256) void gemm_gates() {
    // gates[512][1024] = q_star[512][512] @ Wcomb[1024][512]^T + bias
    gemm_nt_body(g_qstar, g_Wc, g_bias, g_gates, G4, K2H);
}

__global__ __launch_bounds__(256) void gemm_out(const float* __restrict__ W_out,
                                                const float* __restrict__ b_out,
                                                float* __restrict__ out) {
    // out[512][256] = q_star[512][512] @ W_out[256][512]^T + b_out
    gemm_nt_body(g_qstar, W_out, b_out, out, H, K2H);
}

// ---------------- launcher ----------------
extern "C" void kernel_launch(void* const* d_in, const int* in_sizes, int n_in,
                              void* d_out, int out_size) {
    const float* x     = (const float*)d_in[0];
    const void*  batch = d_in[1];
    const float* W_ih  = (const float*)d_in[2];
    const float* W_hh  = (const float*)d_in[3];
    const float* b_ih  = (const float*)d_in[4];
    const float* b_hh  = (const float*)d_in[5];
    const float* W_out = (const float*)d_in[6];
    const float* b_out = (const float*)d_in[7];
    float* out = (float*)d_out;
    int n = in_sizes[0] / H;

    prep_kernel<<<(G4 * K2H + 255) / 256, 256>>>(W_ih, W_hh, b_ih, b_hh);
    seg_kernel<<<3, 256>>>(batch, n);

    // step 1: gates = bias (q_star = hs = 0)
    lstm_first<<<NB, 256>>>();
    attn_kernel<<<NB, 512>>>(x);

    // steps 2..3
    for (int s = 1; s < 3; s++) {
        gemm_gates<<<dim3(G4 / BN, NB / BM), 256>>>();
        lstm_step<<<NB, 256>>>();
        attn_kernel<<<NB, 512>>>(x);
    }

    gemm_out<<<dim3(H / BN, NB / BM), 256>>>(W_out, b_out, out);
}

// round 7
// speedup vs baseline: 1.2718x; 1.1740x over previous
#include <cuda_runtime.h>
#include <math.h>

#define H      256
#define NB     512      // n_graphs
#define G4     1024     // 4*H
#define K2H    512      // 2*H
#define CHB    608      // attention chunk blocks (4 per SM x 152)
#define MAXP   8        // max partials per graph (<=3 actually occur)

// ---------------- device scratch (no allocation allowed) ----------------
__device__ __align__(16) float g_Wc[G4 * K2H];     // combined gate weight [1024][512]
__device__ __align__(16) float g_bias[G4];         // b_ih + b_hh
__device__ __align__(16) float g_hs[NB * H];
__device__ __align__(16) float g_cs[NB * H];
__device__ __align__(16) float g_qstar[NB * K2H];  // [hs, r]
__device__ __align__(16) float g_gates[NB * G4];
__device__ int   g_seg[NB + 1];
__device__ int   g_cnt[NB];                        // partial slot counters (reset by combine)
__device__ float g_pm[NB * MAXP];                  // partial max
__device__ float g_pd[NB * MAXP];                  // partial denom (rel. to pm)
__device__ __align__(16) float g_pr[NB * MAXP * H];// partial weighted sum (rel. to pm)

// ---------------- prep: Wcomb = [W_ih[:,:H]+W_hh | W_ih[:,H:]], bias, seg starts ----------------
__global__ void prep_kernel(const float* __restrict__ W_ih, const float* __restrict__ W_hh,
                            const float* __restrict__ b_ih, const float* __restrict__ b_hh,
                            const void* __restrict__ batch_raw, int n) {
    int i = blockIdx.x * blockDim.x + threadIdx.x;
    if (i < G4 * K2H) {
        int j = i >> 9;      // row (gate index)
        int k = i & 511;     // col
        float v = W_ih[i];
        if (k < H) v += W_hh[j * H + k];
        g_Wc[i] = v;
    }
    if (i < G4) g_bias[i] = b_ih[i] + b_hh[i];
    if (i <= NB) {
        // lower_bound(i) over sorted batch; dtype-agnostic (int32 vs int64)
        const int* b32 = (const int*)batch_raw;
        bool is64 = (b32[n - 1] == 0);   // int64 view: high word of last elem (<512)
        int lo = 0, hi = n;
        if (is64) {
            const long long* b64 = (const long long*)batch_raw;
            long long gv = (long long)i;
            while (lo < hi) { int mid = (lo + hi) >> 1; if (b64[mid] < gv) lo = mid + 1; else hi = mid; }
        } else {
            while (lo < hi) { int mid = (lo + hi) >> 1; if (b32[mid] < i) lo = mid + 1; else hi = mid; }
        }
        g_seg[i] = lo;
    }
}

__device__ __forceinline__ float sigf(float v) { return 1.0f / (1.0f + __expf(-v)); }

// ---------------- LSTM step 1: q_star = hs = 0 -> gates = bias only ----------------
__global__ void lstm_first() {
    int idx = blockIdx.x * blockDim.x + threadIdx.x;   // NB*H
    int t = idx & (H - 1);
    float ig = g_bias[t], gg = g_bias[2 * H + t], og = g_bias[3 * H + t];
    float c = sigf(ig) * tanhf(gg);        // f-gate * cs(=0) drops out
    float h = sigf(og) * tanhf(c);
    g_cs[idx] = c;
    g_hs[idx] = h;
}

// ---------------- LSTM steps 2..: consume g_gates ----------------
__global__ void lstm_step() {
    int idx = blockIdx.x * blockDim.x + threadIdx.x;   // NB*H
    int g = idx >> 8;
    int t = idx & (H - 1);
    const float* gr = g_gates + g * G4;
    float ig = gr[t], fg = gr[H + t], gg = gr[2 * H + t], og = gr[3 * H + t];
    float c = sigf(fg) * g_cs[idx] + sigf(ig) * tanhf(gg);
    float h = sigf(og) * tanhf(c);
    g_cs[idx] = c;
    g_hs[idx] = h;
}

// ---------------- balanced attention pass 1: equal node chunks -> per-graph partials ----------------
// 608 blocks x 256 thr. Each block streams a contiguous chunk of nodes (spans 1-3
// graphs). Per sub-segment: 8 warps x 2-node unroll online softmax, block merge,
// flush unnormalized partial (M, D, r[256]) to a slot from atomicAdd(g_cnt[g]).
__global__ __launch_bounds__(256, 4) void attn_partial(const float* __restrict__ x, int n, int chunk) {
    int c0 = blockIdx.x * chunk;
    if (c0 >= n) return;
    int c1 = min(n, c0 + chunk);
    int warp = threadIdx.x >> 5, lane = threadIdx.x & 31;
    int t = threadIdx.x;

    // find g with seg[g] <= c0 < seg[g+1]
    int lo = 0, hi = NB - 1;
    while (lo < hi) { int mid = (lo + hi + 1) >> 1; if (g_seg[mid] <= c0) lo = mid; else hi = mid - 1; }
    int g = lo;

    __shared__ float sm_m[8], sm_d[8];
    __shared__ float sm_r[8][H];
    __shared__ int sm_slot;

    while (c0 < c1) {
        int segend = g_seg[g + 1];
        int e = min(segend, c1);

        const float4* qv = reinterpret_cast<const float4*>(g_hs + g * H);
        float4 q0 = qv[lane * 2];
        float4 q1 = qv[lane * 2 + 1];

        float m = -3.0e38f, d = 0.0f;
        float r0 = 0.f, r1 = 0.f, r2 = 0.f, r3 = 0.f, r4 = 0.f, r5 = 0.f, r6 = 0.f, r7 = 0.f;

        int i = c0 + warp * 2;
        for (; i + 1 < e; i += 16) {
            const float4* xv0 = reinterpret_cast<const float4*>(x + (size_t)i * H);
            const float4* xv1 = reinterpret_cast<const float4*>(x + (size_t)(i + 1) * H);
            float4 a0 = xv0[lane * 2];
            float4 b0 = xv0[lane * 2 + 1];
            float4 a1 = xv1[lane * 2];
            float4 b1 = xv1[lane * 2 + 1];

            float p0 = a0.x * q0.x + a0.y * q0.y + a0.z * q0.z + a0.w * q0.w
                     + b0.x * q1.x + b0.y * q1.y + b0.z * q1.z + b0.w * q1.w;
            float p1 = a1.x * q0.x + a1.y * q0.y + a1.z * q0.z + a1.w * q0.w
                     + b1.x * q1.x + b1.y * q1.y + b1.z * q1.z + b1.w * q1.w;
            #pragma unroll
            for (int o = 16; o > 0; o >>= 1) {
                p0 += __shfl_xor_sync(0xffffffffu, p0, o);
                p1 += __shfl_xor_sync(0xffffffffu, p1, o);
            }
            if (p0 > m) {
                float f = __expf(m - p0);
                d *= f; r0 *= f; r1 *= f; r2 *= f; r3 *= f; r4 *= f; r5 *= f; r6 *= f; r7 *= f;
                m = p0;
            }
            float w = __expf(p0 - m);
            d += w;
            r0 = fmaf(w, a0.x, r0); r1 = fmaf(w, a0.y, r1);
            r2 = fmaf(w, a0.z, r2); r3 = fmaf(w, a0.w, r3);
            r4 = fmaf(w, b0.x, r4); r5 = fmaf(w, b0.y, r5);
            r6 = fmaf(w, b0.z, r6); r7 = fmaf(w, b0.w, r7);
            if (p1 > m) {
                float f = __expf(m - p1);
                d *= f; r0 *= f; r1 *= f; r2 *= f; r3 *= f; r4 *= f; r5 *= f; r6 *= f; r7 *= f;
                m = p1;
            }
            w = __expf(p1 - m);
            d += w;
            r0 = fmaf(w, a1.x, r0); r1 = fmaf(w, a1.y, r1);
            r2 = fmaf(w, a1.z, r2); r3 = fmaf(w, a1.w, r3);
            r4 = fmaf(w, b1.x, r4); r5 = fmaf(w, b1.y, r5);
            r6 = fmaf(w, b1.z, r6); r7 = fmaf(w, b1.w, r7);
        }
        if (i < e) {
            const float4* xv0 = reinterpret_cast<const float4*>(x + (size_t)i * H);
            float4 a0 = xv0[lane * 2];
            float4 b0 = xv0[lane * 2 + 1];
            float p0 = a0.x * q0.x + a0.y * q0.y + a0.z * q0.z + a0.w * q0.w
                     + b0.x * q1.x + b0.y * q1.y + b0.z * q1.z + b0.w * q1.w;
            #pragma unroll
            for (int o = 16; o > 0; o >>= 1) p0 += __shfl_xor_sync(0xffffffffu, p0, o);
            if (p0 > m) {
                float f = __expf(m - p0);
                d *= f; r0 *= f; r1 *= f; r2 *= f; r3 *= f; r4 *= f; r5 *= f; r6 *= f; r7 *= f;
                m = p0;
            }
            float w = __expf(p0 - m);
            d += w;
            r0 = fmaf(w, a0.x, r0); r1 = fmaf(w, a0.y, r1);
            r2 = fmaf(w, a0.z, r2); r3 = fmaf(w, a0.w, r3);
            r4 = fmaf(w, b0.x, r4); r5 = fmaf(w, b0.y, r5);
            r6 = fmaf(w, b0.z, r6); r7 = fmaf(w, b0.w, r7);
        }

        // block-level merge of 8 warps
        if (lane == 0) { sm_m[warp] = m; sm_d[warp] = d; }
        __syncthreads();
        float M = sm_m[0];
        #pragma unroll
        for (int w = 1; w < 8; w++) M = fmaxf(M, sm_m[w]);
        float D = 0.f;
        #pragma unroll
        for (int w = 0; w < 8; w++) D += sm_d[w] * __expf(sm_m[w] - M);

        float sc = __expf(m - M);   // 0 for warps with no nodes
        int base = lane * 8;
        sm_r[warp][base + 0] = r0 * sc; sm_r[warp][base + 1] = r1 * sc;
        sm_r[warp][base + 2] = r2 * sc; sm_r[warp][base + 3] = r3 * sc;
        sm_r[warp][base + 4] = r4 * sc; sm_r[warp][base + 5] = r5 * sc;
        sm_r[warp][base + 6] = r6 * sc; sm_r[warp][base + 7] = r7 * sc;
        if (t == 0) sm_slot = atomicAdd(&g_cnt[g], 1);
        __syncthreads();

        float R = 0.f;
        #pragma unroll
        for (int w = 0; w < 8; w++) R += sm_r[w][t];
        int p = g * MAXP + sm_slot;
        g_pr[(size_t)p * H + t] = R;              // unnormalized, relative to M
        if (t == 0) { g_pm[p] = M; g_pd[p] = D; }
        __syncthreads();   // protect smem reuse for next sub-segment

        c0 = e;
        if (e == segend) g++;
    }
}

// ---------------- attention pass 2: combine partials, normalize, write q_star ----------------
__global__ void attn_combine() {
    int g = blockIdx.x;
    int t = threadIdx.x;    // 256
    int cnt = g_cnt[g];
    float M = -3.0e38f;
    for (int p = 0; p < cnt; p++) M = fmaxf(M, g_pm[g * MAXP + p]);
    float D = 0.f, R = 0.f;
    for (int p = 0; p < cnt; p++) {
        float f = __expf(g_pm[g * MAXP + p] - M);
        D += g_pd[g * MAXP + p] * f;
        R += g_pr[(size_t)(g * MAXP + p) * H + t] * f;
    }
    R = (D > 0.f) ? (R / D) : 0.f;
    g_qstar[g * K2H + t]     = g_hs[g * H + t];   // q half
    g_qstar[g * K2H + H + t] = R;                 // r half
    if (t == 0) g_cnt[g] = 0;                     // reset for next step / replay
}

// ---------------- tiled fp32 NT GEMM: float4 LDS + register prefetch ----------------
// C[M][N] = A[M][K] @ B[N][K]^T + bias[N]
#define BM 64
#define BN 64
#define BKK 16

__device__ __forceinline__ void gemm_nt_body(const float* __restrict__ A,
                                             const float* __restrict__ Bm,
                                             const float* __restrict__ bias,
                                             float* __restrict__ C,
                                             int Ndim, int Kdim) {
    __shared__ __align__(16) float sA[BKK][BM];
    __shared__ __align__(16) float sB[BKK][BN];
    int tid = threadIdx.x;
    int tx = tid & 15, ty = tid >> 4;
    int row0 = blockIdx.y * BM, col0 = blockIdx.x * BN;
    int lr = tid >> 2;          // 0..63 row within tile
    int lk = (tid & 3) * 4;     // 0,4,8,12 k offset within chunk
    float acc[4][4] = {};

    const float* Aptr = A + (size_t)(row0 + lr) * Kdim + lk;
    const float* Bptr = Bm + (size_t)(col0 + lr) * Kdim + lk;
    float4 pa = *(const float4*)Aptr;
    float4 pb = *(const float4*)Bptr;

    for (int k0 = 0; k0 < Kdim; k0 += BKK) {
        sA[lk + 0][lr] = pa.x; sA[lk + 1][lr] = pa.y; sA[lk + 2][lr] = pa.z; sA[lk + 3][lr] = pa.w;
        sB[lk + 0][lr] = pb.x; sB[lk + 1][lr] = pb.y; sB[lk + 2][lr] = pb.z; sB[lk + 3][lr] = pb.w;
        __syncthreads();

        if (k0 + BKK < Kdim) {   // prefetch next chunk (overlaps with FMA loop)
            pa = *(const float4*)(Aptr + k0 + BKK);
            pb = *(const float4*)(Bptr + k0 + BKK);
        }

        #pragma unroll
        for (int kk = 0; kk < BKK; kk++) {
            float4 av = *(const float4*)&sA[kk][ty * 4];
            float4 bv = *(const float4*)&sB[kk][tx * 4];
            acc[0][0] = fmaf(av.x, bv.x, acc[0][0]); acc[0][1] = fmaf(av.x, bv.y, acc[0][1]);
            acc[0][2] = fmaf(av.x, bv.z, acc[0][2]); acc[0][3] = fmaf(av.x, bv.w, acc[0][3]);
            acc[1][0] = fmaf(av.y, bv.x, acc[1][0]); acc[1][1] = fmaf(av.y, bv.y, acc[1][1]);
            acc[1][2] = fmaf(av.y, bv.z, acc[1][2]); acc[1][3] = fmaf(av.y, bv.w, acc[1][3]);
            acc[2][0] = fmaf(av.z, bv.x, acc[2][0]); acc[2][1] = fmaf(av.z, bv.y, acc[2][1]);
            acc[2][2] = fmaf(av.z, bv.z, acc[2][2]); acc[2][3] = fmaf(av.z, bv.w, acc[2][3]);
            acc[3][0] = fmaf(av.w, bv.x, acc[3][0]); acc[3][1] = fmaf(av.w, bv.y, acc[3][1]);
            acc[3][2] = fmaf(av.w, bv.z, acc[3][2]); acc[3][3] = fmaf(av.w, bv.w, acc[3][3]);
        }
        __syncthreads();
    }
    #pragma unroll
    for (int i = 0; i < 4; i++) {
        int orow = row0 + ty * 4 + i;
        #pragma unroll
        for (int j = 0; j < 4; j++) {
            int ocol = col0 + tx * 4 + j;
            C[(size_t)orow * Ndim + ocol] = acc[i][j] + bias[ocol];
        }
    }
}

__global__ __launch_bounds__(256) void gemm_gates() {
    // gates[512][1024] = q_star[512][512] @ Wcomb[1024][512]^T + bias
    gemm_nt_body(g_qstar, g_Wc, g_bias, g_gates, G4, K2H);
}

__global__ __launch_bounds__(256) void gemm_out(const float* __restrict__ W_out,
                                                const float* __restrict__ b_out,
                                                float* __restrict__ out) {
    // out[512][256] = q_star[512][512] @ W_out[256][512]^T + b_out
    gemm_nt_body(g_qstar, W_out, b_out, out, H, K2H);
}

// ---------------- launcher ----------------
extern "C" void kernel_launch(void* const* d_in, const int* in_sizes, int n_in,
                              void* d_out, int out_size) {
    const float* x     = (const float*)d_in[0];
    const void*  batch = d_in[1];
    const float* W_ih  = (const float*)d_in[2];
    const float* W_hh  = (const float*)d_in[3];
    const float* b_ih  = (const float*)d_in[4];
    const float* b_hh  = (const float*)d_in[5];
    const float* W_out = (const float*)d_in[6];
    const float* b_out = (const float*)d_in[7];
    float* out = (float*)d_out;
    int n = in_sizes[0] / H;
    int chunk = (n + CHB - 1) / CHB;

    prep_kernel<<<(G4 * K2H + 255) / 256, 256>>>(W_ih, W_hh, b_ih, b_hh, batch, n);

    // step 1: gates = bias (q_star = hs = 0)
    lstm_first<<<NB, 256>>>();
    attn_partial<<<CHB, 256>>>(x, n, chunk);
    attn_combine<<<NB, 256>>>();

    // steps 2..3
    for (int s = 1; s < 3; s++) {
        gemm_gates<<<dim3(G4 / BN, NB / BM), 256>>>();
        lstm_step<<<NB, 256>>>();
        attn_partial<<<CHB, 256>>>(x, n, chunk);
        attn_combine<<<NB, 256>>>();
    }

    gemm_out<<<dim3(H / BN, NB / BM), 256>>>(W_out, b_out, out);
}

// round 8
// speedup vs baseline: 1.4582x; 1.1465x over previous
#include <cuda_runtime.h>
#include <math.h>

#define H      256
#define NB     512      // n_graphs
#define G4     1024     // 4*H
#define K2H    512      // 2*H
#define CHB    608      // attention chunk blocks (4 per SM x 152)
#define MAXP   8        // max partials per graph (<=3 actually occur)

// ---------------- device scratch (no allocation allowed) ----------------
__device__ __align__(16) float g_Wc[G4 * K2H];     // combined gate weight [1024][512]
__device__ __align__(16) float g_bias[G4];         // b_ih + b_hh
__device__ __align__(16) float g_hs[NB * H];
__device__ __align__(16) float g_cs[NB * H];
__device__ __align__(16) float g_qstar[NB * K2H];  // [hs, r]
__device__ __align__(16) float g_gates[NB * G4];
__device__ int   g_seg[NB + 1];
__device__ int   g_cnt[NB];                        // partial slot counters
__device__ int   g_done[NB];                       // completed-partials counters
__device__ int   g_exp[NB];                        // expected partials per graph
__device__ float g_pm[NB * MAXP];                  // partial max
__device__ float g_pd[NB * MAXP];                  // partial denom (rel. to pm)
__device__ __align__(16) float g_pr[NB * MAXP * H];// partial weighted sum (rel. to pm)

// ---------------- prep: Wcomb = [W_ih[:,:H]+W_hh | W_ih[:,H:]], bias, seg starts ----------------
__global__ void prep_kernel(const float* __restrict__ W_ih, const float* __restrict__ W_hh,
                            const float* __restrict__ b_ih, const float* __restrict__ b_hh,
                            const void* __restrict__ batch_raw, int n) {
    int i = blockIdx.x * blockDim.x + threadIdx.x;
    if (i < G4 * K2H) {
        int j = i >> 9;      // row (gate index)
        int k = i & 511;     // col
        float v = W_ih[i];
        if (k < H) v += W_hh[j * H + k];
        g_Wc[i] = v;
    }
    if (i < G4) g_bias[i] = b_ih[i] + b_hh[i];
    if (i <= NB) {
        // lower_bound(i) over sorted batch; dtype-agnostic (int32 vs int64)
        const int* b32 = (const int*)batch_raw;
        bool is64 = (b32[n - 1] == 0);   // int64 view: high word of last elem (<512)
        int lo = 0, hi = n;
        if (is64) {
            const long long* b64 = (const long long*)batch_raw;
            long long gv = (long long)i;
            while (lo < hi) { int mid = (lo + hi) >> 1; if (b64[mid] < gv) lo = mid + 1; else hi = mid; }
        } else {
            while (lo < hi) { int mid = (lo + hi) >> 1; if (b32[mid] < i) lo = mid + 1; else hi = mid; }
        }
        g_seg[i] = lo;
    }
}

__device__ __forceinline__ float sigf(float v) { return 1.0f / (1.0f + __expf(-v)); }

// ---------------- LSTM step 1: q_star = hs = 0 -> gates = bias only ----------------
// Also computes expected-partial counts (seg is ready by now) and seeds q_star.
__global__ void lstm_first(int chunk) {
    int idx = blockIdx.x * blockDim.x + threadIdx.x;   // NB*H
    int g = idx >> 8;
    int t = idx & (H - 1);
    if (t == 0) {
        int s = g_seg[g], e = g_seg[g + 1];
        g_exp[g] = (e > s) ? ((e - 1) / chunk - s / chunk + 1) : 0;
    }
    float ig = g_bias[t], gg = g_bias[2 * H + t], og = g_bias[3 * H + t];
    float c = sigf(ig) * tanhf(gg);        // f-gate * cs(=0) drops out
    float h = sigf(og) * tanhf(c);
    g_cs[idx] = c;
    g_hs[idx] = h;
    g_qstar[g * K2H + t]     = h;          // q half
    g_qstar[g * K2H + H + t] = 0.f;        // r half (combine overwrites; stays 0 if empty graph)
}

// ---------------- LSTM steps 2..: consume g_gates ----------------
__global__ void lstm_step() {
    int idx = blockIdx.x * blockDim.x + threadIdx.x;   // NB*H
    int g = idx >> 8;
    int t = idx & (H - 1);
    const float* gr = g_gates + g * G4;
    float ig = gr[t], fg = gr[H + t], gg = gr[2 * H + t], og = gr[3 * H + t];
    float c = sigf(fg) * g_cs[idx] + sigf(ig) * tanhf(gg);
    float h = sigf(og) * tanhf(c);
    g_cs[idx] = c;
    g_hs[idx] = h;
    g_qstar[g * K2H + t]     = h;
    g_qstar[g * K2H + H + t] = 0.f;
}

// ---------------- balanced attention: equal node chunks -> partials; last block combines ----------------
__global__ __launch_bounds__(256, 4) void attn_partial(const float* __restrict__ x, int n, int chunk) {
    int c0 = blockIdx.x * chunk;
    if (c0 >= n) return;
    int c1 = min(n, c0 + chunk);
    int warp = threadIdx.x >> 5, lane = threadIdx.x & 31;
    int t = threadIdx.x;

    // find g with seg[g] <= c0 < seg[g+1] (max g with seg[g] <= c0)
    int lo = 0, hi = NB - 1;
    while (lo < hi) { int mid = (lo + hi + 1) >> 1; if (g_seg[mid] <= c0) lo = mid; else hi = mid - 1; }
    int g = lo;

    __shared__ float sm_m[8], sm_d[8];
    __shared__ float sm_r[8][H];
    __shared__ int sm_slot;
    __shared__ int sm_last;

    while (c0 < c1) {
        int segend = g_seg[g + 1];
        int e = min(segend, c1);
        if (e > c0) {
            const float4* qv = reinterpret_cast<const float4*>(g_hs + g * H);
            float4 q0 = qv[lane * 2];
            float4 q1 = qv[lane * 2 + 1];

            float m = -3.0e38f, d = 0.0f;
            float r0 = 0.f, r1 = 0.f, r2 = 0.f, r3 = 0.f, r4 = 0.f, r5 = 0.f, r6 = 0.f, r7 = 0.f;

            int i = c0 + warp * 2;
            for (; i + 1 < e; i += 16) {
                const float4* xv0 = reinterpret_cast<const float4*>(x + (size_t)i * H);
                const float4* xv1 = reinterpret_cast<const float4*>(x + (size_t)(i + 1) * H);
                float4 a0 = xv0[lane * 2];
                float4 b0 = xv0[lane * 2 + 1];
                float4 a1 = xv1[lane * 2];
                float4 b1 = xv1[lane * 2 + 1];

                float p0 = a0.x * q0.x + a0.y * q0.y + a0.z * q0.z + a0.w * q0.w
                         + b0.x * q1.x + b0.y * q1.y + b0.z * q1.z + b0.w * q1.w;
                float p1 = a1.x * q0.x + a1.y * q0.y + a1.z * q0.z + a1.w * q0.w
                         + b1.x * q1.x + b1.y * q1.y + b1.z * q1.z + b1.w * q1.w;
                #pragma unroll
                for (int o = 16; o > 0; o >>= 1) {
                    p0 += __shfl_xor_sync(0xffffffffu, p0, o);
                    p1 += __shfl_xor_sync(0xffffffffu, p1, o);
                }
                if (p0 > m) {
                    float f = __expf(m - p0);
                    d *= f; r0 *= f; r1 *= f; r2 *= f; r3 *= f; r4 *= f; r5 *= f; r6 *= f; r7 *= f;
                    m = p0;
                }
                float w = __expf(p0 - m);
                d += w;
                r0 = fmaf(w, a0.x, r0); r1 = fmaf(w, a0.y, r1);
                r2 = fmaf(w, a0.z, r2); r3 = fmaf(w, a0.w, r3);
                r4 = fmaf(w, b0.x, r4); r5 = fmaf(w, b0.y, r5);
                r6 = fmaf(w, b0.z, r6); r7 = fmaf(w, b0.w, r7);
                if (p1 > m) {
                    float f = __expf(m - p1);
                    d *= f; r0 *= f; r1 *= f; r2 *= f; r3 *= f; r4 *= f; r5 *= f; r6 *= f; r7 *= f;
                    m = p1;
                }
                w = __expf(p1 - m);
                d += w;
                r0 = fmaf(w, a1.x, r0); r1 = fmaf(w, a1.y, r1);
                r2 = fmaf(w, a1.z, r2); r3 = fmaf(w, a1.w, r3);
                r4 = fmaf(w, b1.x, r4); r5 = fmaf(w, b1.y, r5);
                r6 = fmaf(w, b1.z, r6); r7 = fmaf(w, b1.w, r7);
            }
            if (i < e) {
                const float4* xv0 = reinterpret_cast<const float4*>(x + (size_t)i * H);
                float4 a0 = xv0[lane * 2];
                float4 b0 = xv0[lane * 2 + 1];
                float p0 = a0.x * q0.x + a0.y * q0.y + a0.z * q0.z + a0.w * q0.w
                         + b0.x * q1.x + b0.y * q1.y + b0.z * q1.z + b0.w * q1.w;
                #pragma unroll
                for (int o = 16; o > 0; o >>= 1) p0 += __shfl_xor_sync(0xffffffffu, p0, o);
                if (p0 > m) {
                    float f = __expf(m - p0);
                    d *= f; r0 *= f; r1 *= f; r2 *= f; r3 *= f; r4 *= f; r5 *= f; r6 *= f; r7 *= f;
                    m = p0;
                }
                float w = __expf(p0 - m);
                d += w;
                r0 = fmaf(w, a0.x, r0); r1 = fmaf(w, a0.y, r1);
                r2 = fmaf(w, a0.z, r2); r3 = fmaf(w, a0.w, r3);
                r4 = fmaf(w, b0.x, r4); r5 = fmaf(w, b0.y, r5);
                r6 = fmaf(w, b0.z, r6); r7 = fmaf(w, b0.w, r7);
            }

            // block-level merge of 8 warps
            if (lane == 0) { sm_m[warp] = m; sm_d[warp] = d; }
            __syncthreads();
            float M = sm_m[0];
            #pragma unroll
            for (int w = 1; w < 8; w++) M = fmaxf(M, sm_m[w]);
            float D = 0.f;
            #pragma unroll
            for (int w = 0; w < 8; w++) D += sm_d[w] * __expf(sm_m[w] - M);

            float sc = __expf(m - M);   // 0 for warps with no nodes
            int base = lane * 8;
            sm_r[warp][base + 0] = r0 * sc; sm_r[warp][base + 1] = r1 * sc;
            sm_r[warp][base + 2] = r2 * sc; sm_r[warp][base + 3] = r3 * sc;
            sm_r[warp][base + 4] = r4 * sc; sm_r[warp][base + 5] = r5 * sc;
            sm_r[warp][base + 6] = r6 * sc; sm_r[warp][base + 7] = r7 * sc;
            if (t == 0) sm_slot = atomicAdd(&g_cnt[g], 1);
            __syncthreads();

            float R = 0.f;
            #pragma unroll
            for (int w = 0; w < 8; w++) R += sm_r[w][t];
            int p = g * MAXP + sm_slot;
            g_pr[(size_t)p * H + t] = R;              // unnormalized, relative to M
            if (t == 0) { g_pm[p] = M; g_pd[p] = D; }

            // last-block-done combine
            __threadfence();
            __syncthreads();
            if (t == 0) sm_last = (atomicAdd(&g_done[g], 1) + 1 == g_exp[g]) ? 1 : 0;
            __syncthreads();
            if (sm_last) {
                __threadfence();
                int cnt = g_exp[g];
                float M2 = -3.0e38f;
                for (int pp = 0; pp < cnt; pp++) M2 = fmaxf(M2, g_pm[g * MAXP + pp]);
                float D2 = 0.f, R2 = 0.f;
                for (int pp = 0; pp < cnt; pp++) {
                    float f = __expf(g_pm[g * MAXP + pp] - M2);
                    D2 += g_pd[g * MAXP + pp] * f;
                    R2 += g_pr[(size_t)(g * MAXP + pp) * H + t] * f;
                }
                R2 = (D2 > 0.f) ? (R2 / D2) : 0.f;
                g_qstar[g * K2H + H + t] = R2;        // r half (q half written by lstm)
                if (t == 0) { g_cnt[g] = 0; g_done[g] = 0; }
            }
            __syncthreads();   // protect smem reuse for next sub-segment
            c0 = e;
        }
        if (e == segend) g++;
    }
}

// ---------------- tf32 tensor-core NT GEMM: C[M][N] = A[M][K] @ B[N][K]^T + bias[N] ----------------
__device__ __forceinline__ unsigned f2tf(float f) {
    unsigned r; asm("cvt.rna.tf32.f32 %0, %1;" : "=r"(r) : "f"(f)); return r;
}
__device__ __forceinline__ void mma_tf32(float* d, const unsigned* a, const unsigned* b) {
    asm volatile("mma.sync.aligned.m16n8k8.row.col.f32.tf32.tf32.f32 "
        "{%0,%1,%2,%3}, {%4,%5,%6,%7}, {%8,%9}, {%0,%1,%2,%3};"
        : "+f"(d[0]), "+f"(d[1]), "+f"(d[2]), "+f"(d[3])
        : "r"(a[0]), "r"(a[1]), "r"(a[2]), "r"(a[3]), "r"(b[0]), "r"(b[1]));
}

// block = 64x64 tile, 256 thr (8 warps in 2M x 4N grid; warp tile 32x16), BK=32, Kdim=512
__device__ __forceinline__ void gemm_mma_body(const float* __restrict__ A,
                                              const float* __restrict__ Bm,
                                              const float* __restrict__ bias,
                                              float* __restrict__ C, int Ndim) {
    const int Kdim = K2H;
    __shared__ unsigned sA[64][36];   // [row][k], stride 36 -> conflict-free frag loads
    __shared__ unsigned sB[64][36];   // [n][k]
    int tid = threadIdx.x;
    int lane = tid & 31, warp = tid >> 5;
    int wm = (warp & 1) * 32, wn = (warp >> 1) * 16;
    int row0 = blockIdx.y * 64, col0 = blockIdx.x * 64;
    int lr = tid >> 2, kq = (tid & 3) * 8;
    int fr = lane >> 2, fc = lane & 3;

    const float* Apf = A + (size_t)(row0 + lr) * Kdim + kq;
    const float* Bpf = Bm + (size_t)(col0 + lr) * Kdim + kq;
    float4 pa0 = *(const float4*)Apf;
    float4 pa1 = *(const float4*)(Apf + 4);
    float4 pb0 = *(const float4*)Bpf;
    float4 pb1 = *(const float4*)(Bpf + 4);

    float acc[2][2][4] = {};

    for (int k0 = 0; k0 < Kdim; k0 += 32) {
        sA[lr][kq + 0] = f2tf(pa0.x); sA[lr][kq + 1] = f2tf(pa0.y);
        sA[lr][kq + 2] = f2tf(pa0.z); sA[lr][kq + 3] = f2tf(pa0.w);
        sA[lr][kq + 4] = f2tf(pa1.x); sA[lr][kq + 5] = f2tf(pa1.y);
        sA[lr][kq + 6] = f2tf(pa1.z); sA[lr][kq + 7] = f2tf(pa1.w);
        sB[lr][kq + 0] = f2tf(pb0.x); sB[lr][kq + 1] = f2tf(pb0.y);
        sB[lr][kq + 2] = f2tf(pb0.z); sB[lr][kq + 3] = f2tf(pb0.w);
        sB[lr][kq + 4] = f2tf(pb1.x); sB[lr][kq + 5] = f2tf(pb1.y);
        sB[lr][kq + 6] = f2tf(pb1.z); sB[lr][kq + 7] = f2tf(pb1.w);
        __syncthreads();

        if (k0 + 32 < Kdim) {   // prefetch next chunk
            pa0 = *(const float4*)(Apf + k0 + 32);
            pa1 = *(const float4*)(Apf + k0 + 36);
            pb0 = *(const float4*)(Bpf + k0 + 32);
            pb1 = *(const float4*)(Bpf + k0 + 36);
        }

        #pragma unroll
        for (int ks = 0; ks < 4; ks++) {
            int kc = ks * 8 + fc;
            unsigned a0[4] = { sA[wm + fr][kc],      sA[wm + fr + 8][kc],
                               sA[wm + fr][kc + 4],  sA[wm + fr + 8][kc + 4] };
            unsigned a1[4] = { sA[wm + 16 + fr][kc],     sA[wm + 24 + fr][kc],
                               sA[wm + 16 + fr][kc + 4], sA[wm + 24 + fr][kc + 4] };
            unsigned b0[2] = { sB[wn + fr][kc], sB[wn + fr][kc + 4] };
            unsigned b1[2] = { sB[wn + 8 + fr][kc], sB[wn + 8 + fr][kc + 4] };
            mma_tf32(acc[0][0], a0, b0);
            mma_tf32(acc[0][1], a0, b1);
            mma_tf32(acc[1][0], a1, b0);
            mma_tf32(acc[1][1], a1, b1);
        }
        __syncthreads();
    }

    #pragma unroll
    for (int mm = 0; mm < 2; mm++)
    #pragma unroll
    for (int nn = 0; nn < 2; nn++) {
        int rb = row0 + wm + mm * 16 + fr;
        int cb = col0 + wn + nn * 8 + fc * 2;
        float2 bz = *(const float2*)&bias[cb];
        float2 v0 = { acc[mm][nn][0] + bz.x, acc[mm][nn][1] + bz.y };
        float2 v1 = { acc[mm][nn][2] + bz.x, acc[mm][nn][3] + bz.y };
        *(float2*)&C[(size_t)rb * Ndim + cb] = v0;
        *(float2*)&C[(size_t)(rb + 8) * Ndim + cb] = v1;
    }
}

__global__ __launch_bounds__(256) void gemm_gates() {
    // gates[512][1024] = q_star[512][512] @ Wcomb[1024][512]^T + bias
    gemm_mma_body(g_qstar, g_Wc, g_bias, g_gates, G4);
}

__global__ __launch_bounds__(256) void gemm_out(const float* __restrict__ W_out,
                                                const float* __restrict__ b_out,
                                                float* __restrict__ out) {
    // out[512][256] = q_star[512][512] @ W_out[256][512]^T + b_out
    gemm_mma_body(g_qstar, W_out, b_out, out, H);
}

// ---------------- launcher ----------------
extern "C" void kernel_launch(void* const* d_in, const int* in_sizes, int n_in,
                              void* d_out, int out_size) {
    const float* x     = (const float*)d_in[0];
    const void*  batch = d_in[1];
    const float* W_ih  = (const float*)d_in[2];
    const float* W_hh  = (const float*)d_in[3];
    const float* b_ih  = (const float*)d_in[4];
    const float* b_hh  = (const float*)d_in[5];
    const float* W_out = (const float*)d_in[6];
    const float* b_out = (const float*)d_in[7];
    float* out = (float*)d_out;
    int n = in_sizes[0] / H;
    int chunk = (n + CHB - 1) / CHB;

    prep_kernel<<<(G4 * K2H + 255) / 256, 256>>>(W_ih, W_hh, b_ih, b_hh, batch, n);

    // step 1: gates = bias (q_star = hs = 0)
    lstm_first<<<NB, 256>>>(chunk);
    attn_partial<<<CHB, 256>>>(x, n, chunk);

    // steps 2..3
    for (int s = 1; s < 3; s++) {
        gemm_gates<<<dim3(G4 / 64, NB / 64), 256>>>();
        lstm_step<<<NB, 256>>>();
        attn_partial<<<CHB, 256>>>(x, n, chunk);
    }

    gemm_out<<<dim3(H / 64, NB / 64), 256>>>(W_out, b_out, out);
}

// round 12
// speedup vs baseline: 1.6130x; 1.1062x over previous
#include <cuda_runtime.h>
#include <math.h>

#define H      256
#define NB     512      // n_graphs
#define G4     1024     // 4*H
#define K2H    512      // 2*H
#define CHB    608      // attention chunk blocks (4 per SM x 152)
#define MAXP   8        // max partials per graph (<=3 actually occur)

// ---------------- device scratch (no allocation allowed) ----------------
__device__ __align__(16) float g_Wc[G4 * K2H];     // combined gate weight [1024][512]
__device__ __align__(16) float g_bias[G4];         // b_ih + b_hh
__device__ __align__(16) float g_hs[NB * H];
__device__ __align__(16) float g_cs[NB * H];
__device__ __align__(16) float g_qstar[NB * K2H];  // [hs, r]
__device__ __align__(16) float g_gates2[2 * NB * G4]; // split-K partial gates
__device__ __align__(16) float g_out4[4 * NB * H];    // split-K partial out
__device__ int   g_seg[NB + 1];
__device__ int   g_cnt[NB];                        // partial slot counters
__device__ int   g_done[NB];                       // completed-partials counters
__device__ int   g_exp[NB];                        // expected partials per graph
__device__ float g_pm[NB * MAXP];                  // partial max
__device__ float g_pd[NB * MAXP];                  // partial denom (rel. to pm)
__device__ __align__(16) float g_pr[NB * MAXP * H];// partial weighted sum (rel. to pm)

// ---------------- prep: Wcomb = [W_ih[:,:H]+W_hh | W_ih[:,H:]], bias, seg starts ----------------
__global__ void prep_kernel(const float* __restrict__ W_ih, const float* __restrict__ W_hh,
                            const float* __restrict__ b_ih, const float* __restrict__ b_hh,
                            const void* __restrict__ batch_raw, int n) {
    int i = blockIdx.x * blockDim.x + threadIdx.x;
    if (i < G4 * K2H) {
        int j = i >> 9;      // row (gate index)
        int k = i & 511;     // col
        float v = W_ih[i];
        if (k < H) v += W_hh[j * H + k];
        g_Wc[i] = v;
    }
    if (i < G4) g_bias[i] = b_ih[i] + b_hh[i];
    if (i <= NB) {
        // lower_bound(i) over sorted batch; dtype-agnostic (int32 vs int64)
        const int* b32 = (const int*)batch_raw;
        bool is64 = (b32[n - 1] == 0);   // int64 view: high word of last elem (<512)
        int lo = 0, hi = n;
        if (is64) {
            const long long* b64 = (const long long*)batch_raw;
            long long gv = (long long)i;
            while (lo < hi) { int mid = (lo + hi) >> 1; if (b64[mid] < gv) lo = mid + 1; else hi = mid; }
        } else {
            while (lo < hi) { int mid = (lo + hi) >> 1; if (b32[mid] < i) lo = mid + 1; else hi = mid; }
        }
        g_seg[i] = lo;
    }
}

__device__ __forceinline__ float sigf(float v) { return 1.0f / (1.0f + __expf(-v)); }

// ---------------- LSTM step 1: q_star = hs = 0 -> gates = bias only ----------------
__global__ void lstm_first(int chunk) {
    int idx = blockIdx.x * blockDim.x + threadIdx.x;   // NB*H
    int g = idx >> 8;
    int t = idx & (H - 1);
    if (t == 0) {
        int s = g_seg[g], e = g_seg[g + 1];
        g_exp[g] = (e > s) ? ((e - 1) / chunk - s / chunk + 1) : 0;
    }
    float ig = g_bias[t], gg = g_bias[2 * H + t], og = g_bias[3 * H + t];
    float c = sigf(ig) * tanhf(gg);        // f-gate * cs(=0) drops out
    float h = sigf(og) * tanhf(c);
    g_cs[idx] = c;
    g_hs[idx] = h;
    g_qstar[g * K2H + t]     = h;          // q half
    g_qstar[g * K2H + H + t] = 0.f;        // r half (combine overwrites; stays 0 if empty graph)
}

// ---------------- LSTM steps 2..: sum split-K gate partials + bias ----------------
__global__ void lstm_step() {
    int idx = blockIdx.x * blockDim.x + threadIdx.x;   // NB*H
    int g = idx >> 8;
    int t = idx & (H - 1);
    const float* gr0 = g_gates2 + g * G4;
    const float* gr1 = g_gates2 + NB * G4 + g * G4;
    float ig = gr0[t]         + gr1[t]         + g_bias[t];
    float fg = gr0[H + t]     + gr1[H + t]     + g_bias[H + t];
    float gg = gr0[2 * H + t] + gr1[2 * H + t] + g_bias[2 * H + t];
    float og = gr0[3 * H + t] + gr1[3 * H + t] + g_bias[3 * H + t];
    float c = sigf(fg) * g_cs[idx] + sigf(ig) * tanhf(gg);
    float h = sigf(og) * tanhf(c);
    g_cs[idx] = c;
    g_hs[idx] = h;
    g_qstar[g * K2H + t]     = h;
    g_qstar[g * K2H + H + t] = 0.f;
}

// ---------------- out epilogue: sum 4 split-K partials + bias ----------------
__global__ void out_epi(const float* __restrict__ b_out, float* __restrict__ out) {
    int idx = blockIdx.x * blockDim.x + threadIdx.x;   // NB*H
    int t = idx & (H - 1);
    out[idx] = g_out4[idx] + g_out4[NB * H + idx]
             + g_out4[2 * NB * H + idx] + g_out4[3 * NB * H + idx] + b_out[t];
}

// ---------------- balanced attention: equal node chunks -> partials; last block combines ----------------
__global__ __launch_bounds__(256, 4) void attn_partial(const float* __restrict__ x, int n, int chunk) {
    int c0 = blockIdx.x * chunk;
    if (c0 >= n) return;
    int c1 = min(n, c0 + chunk);
    int warp = threadIdx.x >> 5, lane = threadIdx.x & 31;
    int t = threadIdx.x;

    // find g with seg[g] <= c0 < seg[g+1] (max g with seg[g] <= c0)
    int lo = 0, hi = NB - 1;
    while (lo < hi) { int mid = (lo + hi + 1) >> 1; if (g_seg[mid] <= c0) lo = mid; else hi = mid - 1; }
    int g = lo;

    __shared__ float sm_m[8], sm_d[8];
    __shared__ float sm_r[8][H];
    __shared__ int sm_slot;
    __shared__ int sm_last;

    while (c0 < c1) {
        int segend = g_seg[g + 1];
        int e = min(segend, c1);
        if (e > c0) {
            const float4* qv = reinterpret_cast<const float4*>(g_hs + g * H);
            float4 q0 = qv[lane * 2];
            float4 q1 = qv[lane * 2 + 1];

            float m = -3.0e38f, d = 0.0f;
            float r0 = 0.f, r1 = 0.f, r2 = 0.f, r3 = 0.f, r4 = 0.f, r5 = 0.f, r6 = 0.f, r7 = 0.f;

            int i = c0 + warp * 2;
            for (; i + 1 < e; i += 16) {
                const float4* xv0 = reinterpret_cast<const float4*>(x + (size_t)i * H);
                const float4* xv1 = reinterpret_cast<const float4*>(x + (size_t)(i + 1) * H);
                float4 a0 = xv0[lane * 2];
                float4 b0 = xv0[lane * 2 + 1];
                float4 a1 = xv1[lane * 2];
                float4 b1 = xv1[lane * 2 + 1];

                float p0 = a0.x * q0.x + a0.y * q0.y + a0.z * q0.z + a0.w * q0.w
                         + b0.x * q1.x + b0.y * q1.y + b0.z * q1.z + b0.w * q1.w;
                float p1 = a1.x * q0.x + a1.y * q0.y + a1.z * q0.z + a1.w * q0.w
                         + b1.x * q1.x + b1.y * q1.y + b1.z * q1.z + b1.w * q1.w;
                #pragma unroll
                for (int o = 16; o > 0; o >>= 1) {
                    p0 += __shfl_xor_sync(0xffffffffu, p0, o);
                    p1 += __shfl_xor_sync(0xffffffffu, p1, o);
                }
                if (p0 > m) {
                    float f = __expf(m - p0);
                    d *= f; r0 *= f; r1 *= f; r2 *= f; r3 *= f; r4 *= f; r5 *= f; r6 *= f; r7 *= f;
                    m = p0;
                }
                float w = __expf(p0 - m);
                d += w;
                r0 = fmaf(w, a0.x, r0); r1 = fmaf(w, a0.y, r1);
                r2 = fmaf(w, a0.z, r2); r3 = fmaf(w, a0.w, r3);
                r4 = fmaf(w, b0.x, r4); r5 = fmaf(w, b0.y, r5);
                r6 = fmaf(w, b0.z, r6); r7 = fmaf(w, b0.w, r7);
                if (p1 > m) {
                    float f = __expf(m - p1);
                    d *= f; r0 *= f; r1 *= f; r2 *= f; r3 *= f; r4 *= f; r5 *= f; r6 *= f; r7 *= f;
                    m = p1;
                }
                w = __expf(p1 - m);
                d += w;
                r0 = fmaf(w, a1.x, r0); r1 = fmaf(w, a1.y, r1);
                r2 = fmaf(w, a1.z, r2); r3 = fmaf(w, a1.w, r3);
                r4 = fmaf(w, b1.x, r4); r5 = fmaf(w, b1.y, r5);
                r6 = fmaf(w, b1.z, r6); r7 = fmaf(w, b1.w, r7);
            }
            if (i < e) {
                const float4* xv0 = reinterpret_cast<const float4*>(x + (size_t)i * H);
                float4 a0 = xv0[lane * 2];
                float4 b0 = xv0[lane * 2 + 1];
                float p0 = a0.x * q0.x + a0.y * q0.y + a0.z * q0.z + a0.w * q0.w
                         + b0.x * q1.x + b0.y * q1.y + b0.z * q1.z + b0.w * q1.w;
                #pragma unroll
                for (int o = 16; o > 0; o >>= 1) p0 += __shfl_xor_sync(0xffffffffu, p0, o);
                if (p0 > m) {
                    float f = __expf(m - p0);
                    d *= f; r0 *= f; r1 *= f; r2 *= f; r3 *= f; r4 *= f; r5 *= f; r6 *= f; r7 *= f;
                    m = p0;
                }
                float w = __expf(p0 - m);
                d += w;
                r0 = fmaf(w, a0.x, r0); r1 = fmaf(w, a0.y, r1);
                r2 = fmaf(w, a0.z, r2); r3 = fmaf(w, a0.w, r3);
                r4 = fmaf(w, b0.x, r4); r5 = fmaf(w, b0.y, r5);
                r6 = fmaf(w, b0.z, r6); r7 = fmaf(w, b0.w, r7);
            }

            // block-level merge of 8 warps
            if (lane == 0) { sm_m[warp] = m; sm_d[warp] = d; }
            __syncthreads();
            float M = sm_m[0];
            #pragma unroll
            for (int w = 1; w < 8; w++) M = fmaxf(M, sm_m[w]);
            float D = 0.f;
            #pragma unroll
            for (int w = 0; w < 8; w++) D += sm_d[w] * __expf(sm_m[w] - M);

            float sc = __expf(m - M);   // 0 for warps with no nodes
            int base = lane * 8;
            sm_r[warp][base + 0] = r0 * sc; sm_r[warp][base + 1] = r1 * sc;
            sm_r[warp][base + 2] = r2 * sc; sm_r[warp][base + 3] = r3 * sc;
            sm_r[warp][base + 4] = r4 * sc; sm_r[warp][base + 5] = r5 * sc;
            sm_r[warp][base + 6] = r6 * sc; sm_r[warp][base + 7] = r7 * sc;
            if (t == 0) sm_slot = atomicAdd(&g_cnt[g], 1);
            __syncthreads();

            float R = 0.f;
            #pragma unroll
            for (int w = 0; w < 8; w++) R += sm_r[w][t];
            int p = g * MAXP + sm_slot;
            g_pr[(size_t)p * H + t] = R;              // unnormalized, relative to M
            if (t == 0) { g_pm[p] = M; g_pd[p] = D; }

            // last-block-done combine
            __threadfence();
            __syncthreads();
            if (t == 0) sm_last = (atomicAdd(&g_done[g], 1) + 1 == g_exp[g]) ? 1 : 0;
            __syncthreads();
            if (sm_last) {
                __threadfence();
                int cnt = g_exp[g];
                float M2 = -3.0e38f;
                for (int pp = 0; pp < cnt; pp++) M2 = fmaxf(M2, g_pm[g * MAXP + pp]);
                float D2 = 0.f, R2 = 0.f;
                for (int pp = 0; pp < cnt; pp++) {
                    float f = __expf(g_pm[g * MAXP + pp] - M2);
                    D2 += g_pd[g * MAXP + pp] * f;
                    R2 += g_pr[(size_t)(g * MAXP + pp) * H + t] * f;
                }
                R2 = (D2 > 0.f) ? (R2 / D2) : 0.f;
                g_qstar[g * K2H + H + t] = R2;        // r half (q half written by lstm)
                if (t == 0) { g_cnt[g] = 0; g_done[g] = 0; }
            }
            __syncthreads();   // protect smem reuse for next sub-segment
            c0 = e;
        }
        if (e == segend) g++;
    }
}

// ---------------- tf32 tensor-core NT GEMM, split-K + double-buffered smem ----------------
__device__ __forceinline__ unsigned f2tf(float f) {
    unsigned r; asm("cvt.rna.tf32.f32 %0, %1;" : "=r"(r) : "f"(f)); return r;
}
__device__ __forceinline__ void mma_tf32(float* d, const unsigned* a, const unsigned* b) {
    asm volatile("mma.sync.aligned.m16n8k8.row.col.f32.tf32.tf32.f32 "
        "{%0,%1,%2,%3}, {%4,%5,%6,%7}, {%8,%9}, {%0,%1,%2,%3};"
        : "+f"(d[0]), "+f"(d[1]), "+f"(d[2]), "+f"(d[3])
        : "r"(a[0]), "r"(a[1]), "r"(a[2]), "r"(a[3]), "r"(b[0]), "r"(b[1]));
}

// block = 64x64 output tile, 256 thr (8 warps 2Mx4N; warp tile 32x16), BK=32.
// Computes partial C (no bias) over K range [kbase, kbase+ksteps*32).
__device__ __forceinline__ void gemm_mma_body(const float* __restrict__ A,
                                              const float* __restrict__ Bm,
                                              float* __restrict__ C, int Ndim,
                                              int kbase, int nsteps) {
    __shared__ unsigned sA[2][64][36];   // stride 36 -> conflict-light frag loads
    __shared__ unsigned sB[2][64][36];
    int tid = threadIdx.x;
    int lane = tid & 31, warp = tid >> 5;
    int wm = (warp & 1) * 32, wn = (warp >> 1) * 16;
    int row0 = blockIdx.y * 64, col0 = blockIdx.x * 64;
    int lr = tid >> 2, kq = (tid & 3) * 8;
    int fr = lane >> 2, fc = lane & 3;

    const float* Apf = A + (size_t)(row0 + lr) * K2H + kbase + kq;
    const float* Bpf = Bm + (size_t)(col0 + lr) * K2H + kbase + kq;

    // fill buffer 0 with chunk 0
    {
        float4 a0 = *(const float4*)Apf;
        float4 a1 = *(const float4*)(Apf + 4);
        float4 b0 = *(const float4*)Bpf;
        float4 b1 = *(const float4*)(Bpf + 4);
        sA[0][lr][kq + 0] = f2tf(a0.x); sA[0][lr][kq + 1] = f2tf(a0.y);
        sA[0][lr][kq + 2] = f2tf(a0.z); sA[0][lr][kq + 3] = f2tf(a0.w);
        sA[0][lr][kq + 4] = f2tf(a1.x); sA[0][lr][kq + 5] = f2tf(a1.y);
        sA[0][lr][kq + 6] = f2tf(a1.z); sA[0][lr][kq + 7] = f2tf(a1.w);
        sB[0][lr][kq + 0] = f2tf(b0.x); sB[0][lr][kq + 1] = f2tf(b0.y);
        sB[0][lr][kq + 2] = f2tf(b0.z); sB[0][lr][kq + 3] = f2tf(b0.w);
        sB[0][lr][kq + 4] = f2tf(b1.x); sB[0][lr][kq + 5] = f2tf(b1.y);
        sB[0][lr][kq + 6] = f2tf(b1.z); sB[0][lr][kq + 7] = f2tf(b1.w);
    }
    __syncthreads();

    float acc[2][2][4] = {};
    float4 pa0, pa1, pb0, pb1;

    for (int s = 0; s < nsteps; s++) {
        int cur = s & 1, nxt = 1 - cur;
        if (s + 1 < nsteps) {   // global prefetch before the MMA burst
            int off = (s + 1) * 32;
            pa0 = *(const float4*)(Apf + off);
            pa1 = *(const float4*)(Apf + off + 4);
            pb0 = *(const float4*)(Bpf + off);
            pb1 = *(const float4*)(Bpf + off + 4);
        }

        #pragma unroll
        for (int ks = 0; ks < 4; ks++) {
            int kc = ks * 8 + fc;
            unsigned a0[4] = { sA[cur][wm + fr][kc],      sA[cur][wm + fr + 8][kc],
                               sA[cur][wm + fr][kc + 4],  sA[cur][wm + fr + 8][kc + 4] };
            unsigned a1[4] = { sA[cur][wm + 16 + fr][kc],     sA[cur][wm + 24 + fr][kc],
                               sA[cur][wm + 16 + fr][kc + 4], sA[cur][wm + 24 + fr][kc + 4] };
            unsigned b0[2] = { sB[cur][wn + fr][kc], sB[cur][wn + fr][kc + 4] };
            unsigned b1[2] = { sB[cur][wn + 8 + fr][kc], sB[cur][wn + 8 + fr][kc + 4] };
            mma_tf32(acc[0][0], a0, b0);
            mma_tf32(acc[0][1], a0, b1);
            mma_tf32(acc[1][0], a1, b0);
            mma_tf32(acc[1][1], a1, b1);
        }

        if (s + 1 < nsteps) {   // stage next chunk into the other buffer
            sA[nxt][lr][kq + 0] = f2tf(pa0.x); sA[nxt][lr][kq + 1] = f2tf(pa0.y);
            sA[nxt][lr][kq + 2] = f2tf(pa0.z); sA[nxt][lr][kq + 3] = f2tf(pa0.w);
            sA[nxt][lr][kq + 4] = f2tf(pa1.x); sA[nxt][lr][kq + 5] = f2tf(pa1.y);
            sA[nxt][lr][kq + 6] = f2tf(pa1.z); sA[nxt][lr][kq + 7] = f2tf(pa1.w);
            sB[nxt][lr][kq + 0] = f2tf(pb0.x); sB[nxt][lr][kq + 1] = f2tf(pb0.y);
            sB[nxt][lr][kq + 2] = f2tf(pb0.z); sB[nxt][lr][kq + 3] = f2tf(pb0.w);
            sB[nxt][lr][kq + 4] = f2tf(pb1.x); sB[nxt][lr][kq + 5] = f2tf(pb1.y);
            sB[nxt][lr][kq + 6] = f2tf(pb1.z); sB[nxt][lr][kq + 7] = f2tf(pb1.w);
            __syncthreads();
        }
    }

    #pragma unroll
    for (int mm = 0; mm < 2; mm++)
    #pragma unroll
    for (int nn = 0; nn < 2; nn++) {
        int rb = row0 + wm + mm * 16 + fr;
        int cb = col0 + wn + nn * 8 + fc * 2;
        float2 v0 = { acc[mm][nn][0], acc[mm][nn][1] };
        float2 v1 = { acc[mm][nn][2], acc[mm][nn][3] };
        *(float2*)&C[(size_t)rb * Ndim + cb] = v0;
        *(float2*)&C[(size_t)(rb + 8) * Ndim + cb] = v1;
    }
}

__global__ __launch_bounds__(256) void gemm_gates() {
    // split-K=2: partial gates[z][512][1024] = q_star @ Wcomb^T over K half z
    int z = blockIdx.z;
    gemm_mma_body(g_qstar, g_Wc, g_gates2 + (size_t)z * NB * G4, G4, z * 256, 8);
}

__global__ __launch_bounds__(256) void gemm_out(const float* __restrict__ W_out) {
    // split-K=4: partial out[z][512][256] = q_star @ W_out^T over K quarter z
    int z = blockIdx.z;
    gemm_mma_body(g_qstar, W_out, g_out4 + (size_t)z * NB * H, H, z * 128, 4);
}

// ---------------- launcher ----------------
extern "C" void kernel_launch(void* const* d_in, const int* in_sizes, int n_in,
                              void* d_out, int out_size) {
    const float* x     = (const float*)d_in[0];
    const void*  batch = d_in[1];
    const float* W_ih  = (const float*)d_in[2];
    const float* W_hh  = (const float*)d_in[3];
    const float* b_ih  = (const float*)d_in[4];
    const float* b_hh  = (const float*)d_in[5];
    const float* W_out = (const float*)d_in[6];
    const float* b_out = (const float*)d_in[7];
    float* out = (float*)d_out;
    int n = in_sizes[0] / H;
    int chunk = (n + CHB - 1) / CHB;

    prep_kernel<<<(G4 * K2H + 255) / 256, 256>>>(W_ih, W_hh, b_ih, b_hh, batch, n);

    // step 1: gates = bias (q_star = hs = 0)
    lstm_first<<<NB, 256>>>(chunk);
    attn_partial<<<CHB, 256>>>(x, n, chunk);

    // steps 2..3
    for (int s = 1; s < 3; s++) {
        gemm_gates<<<dim3(G4 / 64, NB / 64, 2), 256>>>();
        lstm_step<<<NB, 256>>>();
        attn_partial<<<CHB, 256>>>(x, n, chunk);
    }

    gemm_out<<<dim3(H / 64, NB / 64, 4), 256>>>(W_out);
    out_epi<<<NB, 256>>>(b_out, out);
}

// round 13
// speedup vs baseline: 1.6177x; 1.0029x over previous
#include <cuda_runtime.h>
#include <math.h>

#define H      256
#define NB     512      // n_graphs
#define G4     1024     // 4*H
#define K2H    512      // 2*H
#define CHB    608      // attention chunk blocks (4 per SM x 152)
#define MAXP   8        // max partials per graph (<=3 actually occur)

// ---------------- device scratch (no allocation allowed) ----------------
__device__ __align__(16) float g_Wc[G4 * K2H];     // combined gate weight [1024][512]
__device__ __align__(16) float g_bias[G4];         // b_ih + b_hh
__device__ __align__(16) float g_hs[NB * H];
__device__ __align__(16) float g_cs[NB * H];
__device__ __align__(16) float g_qstar[NB * K2H];  // [hs, r]
__device__ __align__(16) float g_gates2[2 * NB * G4]; // split-K partial gates
__device__ __align__(16) float g_out4[4 * NB * H];    // split-K partial out
__device__ int   g_seg[NB + 1];
__device__ int   g_cnt[NB];                        // partial slot counters
__device__ int   g_done[NB];                       // completed-partials counters
__device__ int   g_exp[NB];                        // expected partials per graph
__device__ float g_pm[NB * MAXP];                  // partial max
__device__ float g_pd[NB * MAXP];                  // partial denom (rel. to pm)
__device__ __align__(16) float g_pr[NB * MAXP * H];// partial weighted sum (rel. to pm)

__device__ __forceinline__ void dep_sync() {
#if __CUDA_ARCH__ >= 900
    cudaGridDependencySynchronize();
#endif
}

// ---------------- prep: Wcomb = [W_ih[:,:H]+W_hh | W_ih[:,H:]], bias, seg starts ----------------
__global__ void prep_kernel(const float* __restrict__ W_ih, const float* __restrict__ W_hh,
                            const float* __restrict__ b_ih, const float* __restrict__ b_hh,
                            const void* __restrict__ batch_raw, int n) {
    int i = blockIdx.x * blockDim.x + threadIdx.x;   // over G4*K2H/4 = 131072
    if (i < G4 * K2H / 4) {
        int j = i >> 7;              // row (gate index)
        int k4 = (i & 127) * 4;      // col (4-aligned)
        float4 v = *(const float4*)&W_ih[i * 4];
        if (k4 < H) {
            float4 w = *(const float4*)&W_hh[j * H + k4];
            v.x += w.x; v.y += w.y; v.z += w.z; v.w += w.w;
        }
        *(float4*)&g_Wc[i * 4] = v;
    }
    if (i < G4) g_bias[i] = b_ih[i] + b_hh[i];
    if (i <= NB) {
        // lower_bound(i) over sorted batch; dtype-agnostic (int32 vs int64)
        const int* b32 = (const int*)batch_raw;
        bool is64 = (b32[n - 1] == 0);   // int64 view: high word of last elem (<512)
        int lo = 0, hi = n;
        if (is64) {
            const long long* b64 = (const long long*)batch_raw;
            long long gv = (long long)i;
            while (lo < hi) { int mid = (lo + hi) >> 1; if (b64[mid] < gv) lo = mid + 1; else hi = mid; }
        } else {
            while (lo < hi) { int mid = (lo + hi) >> 1; if (b32[mid] < i) lo = mid + 1; else hi = mid; }
        }
        g_seg[i] = lo;
    }
}

__device__ __forceinline__ float sigf(float v) { return 1.0f / (1.0f + __expf(-v)); }

// ---------------- LSTM step 1: q_star = hs = 0 -> gates = bias only ----------------
__global__ void lstm_first(int chunk) {
    dep_sync();
    int idx = blockIdx.x * blockDim.x + threadIdx.x;   // NB*H
    int g = idx >> 8;
    int t = idx & (H - 1);
    if (t == 0) {
        int s = g_seg[g], e = g_seg[g + 1];
        g_exp[g] = (e > s) ? ((e - 1) / chunk - s / chunk + 1) : 0;
    }
    float ig = g_bias[t], gg = g_bias[2 * H + t], og = g_bias[3 * H + t];
    float c = sigf(ig) * tanhf(gg);        // f-gate * cs(=0) drops out
    float h = sigf(og) * tanhf(c);
    g_cs[idx] = c;
    g_hs[idx] = h;
    g_qstar[g * K2H + t]     = h;          // q half
    g_qstar[g * K2H + H + t] = 0.f;        // r half (combine overwrites; stays 0 if empty graph)
}

// ---------------- LSTM steps 2..: sum split-K gate partials + bias ----------------
__global__ void lstm_step() {
    dep_sync();
    int idx = blockIdx.x * blockDim.x + threadIdx.x;   // NB*H
    int g = idx >> 8;
    int t = idx & (H - 1);
    const float* gr0 = g_gates2 + g * G4;
    const float* gr1 = g_gates2 + NB * G4 + g * G4;
    float ig = gr0[t]         + gr1[t]         + g_bias[t];
    float fg = gr0[H + t]     + gr1[H + t]     + g_bias[H + t];
    float gg = gr0[2 * H + t] + gr1[2 * H + t] + g_bias[2 * H + t];
    float og = gr0[3 * H + t] + gr1[3 * H + t] + g_bias[3 * H + t];
    float c = sigf(fg) * g_cs[idx] + sigf(ig) * tanhf(gg);
    float h = sigf(og) * tanhf(c);
    g_cs[idx] = c;
    g_hs[idx] = h;
    g_qstar[g * K2H + t]     = h;
    g_qstar[g * K2H + H + t] = 0.f;
}

// ---------------- out epilogue: sum 4 split-K partials + bias ----------------
__global__ void out_epi(const float* __restrict__ b_out, float* __restrict__ out) {
    dep_sync();
    int idx = blockIdx.x * blockDim.x + threadIdx.x;   // NB*H
    int t = idx & (H - 1);
    out[idx] = g_out4[idx] + g_out4[NB * H + idx]
             + g_out4[2 * NB * H + idx] + g_out4[3 * NB * H + idx] + b_out[t];
}

// ---------------- balanced attention: equal node chunks -> partials; last block combines ----------------
__global__ __launch_bounds__(256, 4) void attn_partial(const float* __restrict__ x, int n, int chunk) {
    int c0 = blockIdx.x * chunk;
    if (c0 >= n) return;
    dep_sync();
    int c1 = min(n, c0 + chunk);
    int warp = threadIdx.x >> 5, lane = threadIdx.x & 31;
    int t = threadIdx.x;

    // find g with seg[g] <= c0 < seg[g+1] (max g with seg[g] <= c0)
    int lo = 0, hi = NB - 1;
    while (lo < hi) { int mid = (lo + hi + 1) >> 1; if (g_seg[mid] <= c0) lo = mid; else hi = mid - 1; }
    int g = lo;

    __shared__ float sm_m[8], sm_d[8];
    __shared__ float sm_r[8][H];
    __shared__ int sm_slot;
    __shared__ int sm_last;

    while (c0 < c1) {
        int segend = g_seg[g + 1];
        int e = min(segend, c1);
        if (e > c0) {
            const float4* qv = reinterpret_cast<const float4*>(g_hs + g * H);
            float4 q0 = qv[lane * 2];
            float4 q1 = qv[lane * 2 + 1];

            float m = -3.0e38f, d = 0.0f;
            float r0 = 0.f, r1 = 0.f, r2 = 0.f, r3 = 0.f, r4 = 0.f, r5 = 0.f, r6 = 0.f, r7 = 0.f;

            int i = c0 + warp * 2;
            for (; i + 1 < e; i += 16) {
                const float4* xv0 = reinterpret_cast<const float4*>(x + (size_t)i * H);
                const float4* xv1 = reinterpret_cast<const float4*>(x + (size_t)(i + 1) * H);
                float4 a0 = xv0[lane * 2];
                float4 b0 = xv0[lane * 2 + 1];
                float4 a1 = xv1[lane * 2];
                float4 b1 = xv1[lane * 2 + 1];

                float p0 = a0.x * q0.x + a0.y * q0.y + a0.z * q0.z + a0.w * q0.w
                         + b0.x * q1.x + b0.y * q1.y + b0.z * q1.z + b0.w * q1.w;
                float p1 = a1.x * q0.x + a1.y * q0.y + a1.z * q0.z + a1.w * q0.w
                         + b1.x * q1.x + b1.y * q1.y + b1.z * q1.z + b1.w * q1.w;
                #pragma unroll
                for (int o = 16; o > 0; o >>= 1) {
                    p0 += __shfl_xor_sync(0xffffffffu, p0, o);
                    p1 += __shfl_xor_sync(0xffffffffu, p1, o);
                }
                if (p0 > m) {
                    float f = __expf(m - p0);
                    d *= f; r0 *= f; r1 *= f; r2 *= f; r3 *= f; r4 *= f; r5 *= f; r6 *= f; r7 *= f;
                    m = p0;
                }
                float w = __expf(p0 - m);
                d += w;
                r0 = fmaf(w, a0.x, r0); r1 = fmaf(w, a0.y, r1);
                r2 = fmaf(w, a0.z, r2); r3 = fmaf(w, a0.w, r3);
                r4 = fmaf(w, b0.x, r4); r5 = fmaf(w, b0.y, r5);
                r6 = fmaf(w, b0.z, r6); r7 = fmaf(w, b0.w, r7);
                if (p1 > m) {
                    float f = __expf(m - p1);
                    d *= f; r0 *= f; r1 *= f; r2 *= f; r3 *= f; r4 *= f; r5 *= f; r6 *= f; r7 *= f;
                    m = p1;
                }
                w = __expf(p1 - m);
                d += w;
                r0 = fmaf(w, a1.x, r0); r1 = fmaf(w, a1.y, r1);
                r2 = fmaf(w, a1.z, r2); r3 = fmaf(w, a1.w, r3);
                r4 = fmaf(w, b1.x, r4); r5 = fmaf(w, b1.y, r5);
                r6 = fmaf(w, b1.z, r6); r7 = fmaf(w, b1.w, r7);
            }
            if (i < e) {
                const float4* xv0 = reinterpret_cast<const float4*>(x + (size_t)i * H);
                float4 a0 = xv0[lane * 2];
                float4 b0 = xv0[lane * 2 + 1];
                float p0 = a0.x * q0.x + a0.y * q0.y + a0.z * q0.z + a0.w * q0.w
                         + b0.x * q1.x + b0.y * q1.y + b0.z * q1.z + b0.w * q1.w;
                #pragma unroll
                for (int o = 16; o > 0; o >>= 1) p0 += __shfl_xor_sync(0xffffffffu, p0, o);
                if (p0 > m) {
                    float f = __expf(m - p0);
                    d *= f; r0 *= f; r1 *= f; r2 *= f; r3 *= f; r4 *= f; r5 *= f; r6 *= f; r7 *= f;
                    m = p0;
                }
                float w = __expf(p0 - m);
                d += w;
                r0 = fmaf(w, a0.x, r0); r1 = fmaf(w, a0.y, r1);
                r2 = fmaf(w, a0.z, r2); r3 = fmaf(w, a0.w, r3);
                r4 = fmaf(w, b0.x, r4); r5 = fmaf(w, b0.y, r5);
                r6 = fmaf(w, b0.z, r6); r7 = fmaf(w, b0.w, r7);
            }

            // block-level merge of 8 warps
            if (lane == 0) { sm_m[warp] = m; sm_d[warp] = d; }
            __syncthreads();
            float M = sm_m[0];
            #pragma unroll
            for (int w = 1; w < 8; w++) M = fmaxf(M, sm_m[w]);
            float D = 0.f;
            #pragma unroll
            for (int w = 0; w < 8; w++) D += sm_d[w] * __expf(sm_m[w] - M);

            float sc = __expf(m - M);   // 0 for warps with no nodes
            int base = lane * 8;
            sm_r[warp][base + 0] = r0 * sc; sm_r[warp][base + 1] = r1 * sc;
            sm_r[warp][base + 2] = r2 * sc; sm_r[warp][base + 3] = r3 * sc;
            sm_r[warp][base + 4] = r4 * sc; sm_r[warp][base + 5] = r5 * sc;
            sm_r[warp][base + 6] = r6 * sc; sm_r[warp][base + 7] = r7 * sc;
            if (t == 0) sm_slot = atomicAdd(&g_cnt[g], 1);
            __syncthreads();

            float R = 0.f;
            #pragma unroll
            for (int w = 0; w < 8; w++) R += sm_r[w][t];
            int p = g * MAXP + sm_slot;
            g_pr[(size_t)p * H + t] = R;              // unnormalized, relative to M
            if (t == 0) { g_pm[p] = M; g_pd[p] = D; }

            // last-block-done combine
            __threadfence();
            __syncthreads();
            if (t == 0) sm_last = (atomicAdd(&g_done[g], 1) + 1 == g_exp[g]) ? 1 : 0;
            __syncthreads();
            if (sm_last) {
                __threadfence();
                int cnt = g_exp[g];
                float M2 = -3.0e38f;
                for (int pp = 0; pp < cnt; pp++) M2 = fmaxf(M2, g_pm[g * MAXP + pp]);
                float D2 = 0.f, R2 = 0.f;
                for (int pp = 0; pp < cnt; pp++) {
                    float f = __expf(g_pm[g * MAXP + pp] - M2);
                    D2 += g_pd[g * MAXP + pp] * f;
                    R2 += g_pr[(size_t)(g * MAXP + pp) * H + t] * f;
                }
                R2 = (D2 > 0.f) ? (R2 / D2) : 0.f;
                g_qstar[g * K2H + H + t] = R2;        // r half (q half written by lstm)
                if (t == 0) { g_cnt[g] = 0; g_done[g] = 0; }
            }
            __syncthreads();   // protect smem reuse for next sub-segment
            c0 = e;
        }
        if (e == segend) g++;
    }
}

// ---------------- tf32 tensor-core NT GEMM helpers ----------------
__device__ __forceinline__ unsigned f2tf(float f) {
    unsigned r; asm("cvt.rna.tf32.f32 %0, %1;" : "=r"(r) : "f"(f)); return r;
}
__device__ __forceinline__ void mma_tf32(float* d, const unsigned* a, const unsigned* b) {
    asm volatile("mma.sync.aligned.m16n8k8.row.col.f32.tf32.tf32.f32 "
        "{%0,%1,%2,%3}, {%4,%5,%6,%7}, {%8,%9}, {%0,%1,%2,%3};"
        : "+f"(d[0]), "+f"(d[1]), "+f"(d[2]), "+f"(d[3])
        : "r"(a[0]), "r"(a[1]), "r"(a[2]), "r"(a[3]), "r"(b[0]), "r"(b[1]));
}

// ---- gates GEMM: 128x64 block tile, 8 warps 4Mx2N (warp tile 32x32), BK=32, split-K=2 ----
// grid (16, 4, 2) = 128 blocks = 1 wave. Partial (no bias).
__global__ __launch_bounds__(256) void gemm_gates() {
    int z = blockIdx.z;
    dep_sync();
    const float* A = g_qstar;
    const float* Bm = g_Wc;
    float* C = g_gates2 + (size_t)z * NB * G4;

    __shared__ unsigned sA[128][36];
    __shared__ unsigned sB[64][36];
    int tid = threadIdx.x, lane = tid & 31, warp = tid >> 5;
    int wm = (warp >> 1) * 32, wn = (warp & 1) * 32;
    int row0 = blockIdx.y * 128, col0 = blockIdx.x * 64;
    int fr = lane >> 2, fc = lane & 3;
    int lra = tid >> 1, kqa = (tid & 1) * 16;   // A: 2 thr/row, 16 floats each
    int lrb = tid >> 2, kqb = (tid & 3) * 8;    // B: 4 thr/row, 8 floats each
    int kbase = z * 256;

    const float* Apf = A + (size_t)(row0 + lra) * K2H + kbase + kqa;
    const float* Bpf = Bm + (size_t)(col0 + lrb) * K2H + kbase + kqb;

    float acc[2][4][4] = {};
    float4 ra[4], rb[2];
    ra[0] = *(const float4*)(Apf + 0);  ra[1] = *(const float4*)(Apf + 4);
    ra[2] = *(const float4*)(Apf + 8);  ra[3] = *(const float4*)(Apf + 12);
    rb[0] = *(const float4*)(Bpf + 0);  rb[1] = *(const float4*)(Bpf + 4);

    for (int s = 0; s < 8; s++) {
        #pragma unroll
        for (int j = 0; j < 4; j++) {
            sA[lra][kqa + 4 * j + 0] = f2tf(ra[j].x);
            sA[lra][kqa + 4 * j + 1] = f2tf(ra[j].y);
            sA[lra][kqa + 4 * j + 2] = f2tf(ra[j].z);
            sA[lra][kqa + 4 * j + 3] = f2tf(ra[j].w);
        }
        #pragma unroll
        for (int j = 0; j < 2; j++) {
            sB[lrb][kqb + 4 * j + 0] = f2tf(rb[j].x);
            sB[lrb][kqb + 4 * j + 1] = f2tf(rb[j].y);
            sB[lrb][kqb + 4 * j + 2] = f2tf(rb[j].z);
            sB[lrb][kqb + 4 * j + 3] = f2tf(rb[j].w);
        }
        __syncthreads();

        if (s < 7) {   // global prefetch for next chunk overlaps the MMA burst
            int off = (s + 1) * 32;
            ra[0] = *(const float4*)(Apf + off + 0);  ra[1] = *(const float4*)(Apf + off + 4);
            ra[2] = *(const float4*)(Apf + off + 8);  ra[3] = *(const float4*)(Apf + off + 12);
            rb[0] = *(const float4*)(Bpf + off + 0);  rb[1] = *(const float4*)(Bpf + off + 4);
        }

        #pragma unroll
        for (int ks = 0; ks < 4; ks++) {
            int kc = ks * 8 + fc;
            unsigned a0[4] = { sA[wm + fr][kc],       sA[wm + 8 + fr][kc],
                               sA[wm + fr][kc + 4],   sA[wm + 8 + fr][kc + 4] };
            unsigned a1[4] = { sA[wm + 16 + fr][kc],     sA[wm + 24 + fr][kc],
                               sA[wm + 16 + fr][kc + 4], sA[wm + 24 + fr][kc + 4] };
            #pragma unroll
            for (int nn = 0; nn < 4; nn++) {
                unsigned b[2] = { sB[wn + nn * 8 + fr][kc], sB[wn + nn * 8 + fr][kc + 4] };
                mma_tf32(acc[0][nn], a0, b);
                mma_tf32(acc[1][nn], a1, b);
            }
        }
        __syncthreads();
    }

    #pragma unroll
    for (int mm = 0; mm < 2; mm++)
    #pragma unroll
    for (int nn = 0; nn < 4; nn++) {
        int rr = row0 + wm + mm * 16 + fr;
        int cb = col0 + wn + nn * 8 + fc * 2;
        float2 v0 = { acc[mm][nn][0], acc[mm][nn][1] };
        float2 v1 = { acc[mm][nn][2], acc[mm][nn][3] };
        *(float2*)&C[(size_t)rr * G4 + cb] = v0;
        *(float2*)&C[(size_t)(rr + 8) * G4 + cb] = v1;
    }
}

// ---- out GEMM: 64x64 tile, 8 warps 2Mx4N (warp tile 32x16), BK=32, split-K=4 ----
__global__ __launch_bounds__(256) void gemm_out(const float* __restrict__ W_out) {
    int z = blockIdx.z;
    dep_sync();
    const float* A = g_qstar;
    const float* Bm = W_out;
    float* C = g_out4 + (size_t)z * NB * H;
    int kbase = z * 128, nsteps = 4;

    __shared__ unsigned sA[2][64][36];
    __shared__ unsigned sB[2][64][36];
    int tid = threadIdx.x;
    int lane = tid & 31, warp = tid >> 5;
    int wm = (warp & 1) * 32, wn = (warp >> 1) * 16;
    int row0 = blockIdx.y * 64, col0 = blockIdx.x * 64;
    int lr = tid >> 2, kq = (tid & 3) * 8;
    int fr = lane >> 2, fc = lane & 3;

    const float* Apf = A + (size_t)(row0 + lr) * K2H + kbase + kq;
    const float* Bpf = Bm + (size_t)(col0 + lr) * K2H + kbase + kq;

    {
        float4 a0 = *(const float4*)Apf;
        float4 a1 = *(const float4*)(Apf + 4);
        float4 b0 = *(const float4*)Bpf;
        float4 b1 = *(const float4*)(Bpf + 4);
        sA[0][lr][kq + 0] = f2tf(a0.x); sA[0][lr][kq + 1] = f2tf(a0.y);
        sA[0][lr][kq + 2] = f2tf(a0.z); sA[0][lr][kq + 3] = f2tf(a0.w);
        sA[0][lr][kq + 4] = f2tf(a1.x); sA[0][lr][kq + 5] = f2tf(a1.y);
        sA[0][lr][kq + 6] = f2tf(a1.z); sA[0][lr][kq + 7] = f2tf(a1.w);
        sB[0][lr][kq + 0] = f2tf(b0.x); sB[0][lr][kq + 1] = f2tf(b0.y);
        sB[0][lr][kq + 2] = f2tf(b0.z); sB[0][lr][kq + 3] = f2tf(b0.w);
        sB[0][lr][kq + 4] = f2tf(b1.x); sB[0][lr][kq + 5] = f2tf(b1.y);
        sB[0][lr][kq + 6] = f2tf(b1.z); sB[0][lr][kq + 7] = f2tf(b1.w);
    }
    __syncthreads();

    float acc[2][2][4] = {};
    float4 pa0, pa1, pb0, pb1;

    for (int s = 0; s < nsteps; s++) {
        int cur = s & 1, nxt = 1 - cur;
        if (s + 1 < nsteps) {
            int off = (s + 1) * 32;
            pa0 = *(const float4*)(Apf + off);
            pa1 = *(const float4*)(Apf + off + 4);
            pb0 = *(const float4*)(Bpf + off);
            pb1 = *(const float4*)(Bpf + off + 4);
        }

        #pragma unroll
        for (int ks = 0; ks < 4; ks++) {
            int kc = ks * 8 + fc;
            unsigned a0[4] = { sA[cur][wm + fr][kc],      sA[cur][wm + fr + 8][kc],
                               sA[cur][wm + fr][kc + 4],  sA[cur][wm + fr + 8][kc + 4] };
            unsigned a1[4] = { sA[cur][wm + 16 + fr][kc],     sA[cur][wm + 24 + fr][kc],
                               sA[cur][wm + 16 + fr][kc + 4], sA[cur][wm + 24 + fr][kc + 4] };
            unsigned b0[2] = { sB[cur][wn + fr][kc], sB[cur][wn + fr][kc + 4] };
            unsigned b1[2] = { sB[cur][wn + 8 + fr][kc], sB[cur][wn + 8 + fr][kc + 4] };
            mma_tf32(acc[0][0], a0, b0);
            mma_tf32(acc[0][1], a0, b1);
            mma_tf32(acc[1][0], a1, b0);
            mma_tf32(acc[1][1], a1, b1);
        }

        if (s + 1 < nsteps) {
            sA[nxt][lr][kq + 0] = f2tf(pa0.x); sA[nxt][lr][kq + 1] = f2tf(pa0.y);
            sA[nxt][lr][kq + 2] = f2tf(pa0.z); sA[nxt][lr][kq + 3] = f2tf(pa0.w);
            sA[nxt][lr][kq + 4] = f2tf(pa1.x); sA[nxt][lr][kq + 5] = f2tf(pa1.y);
            sA[nxt][lr][kq + 6] = f2tf(pa1.z); sA[nxt][lr][kq + 7] = f2tf(pa1.w);
            sB[nxt][lr][kq + 0] = f2tf(pb0.x); sB[nxt][lr][kq + 1] = f2tf(pb0.y);
            sB[nxt][lr][kq + 2] = f2tf(pb0.z); sB[nxt][lr][kq + 3] = f2tf(pb0.w);
            sB[nxt][lr][kq + 4] = f2tf(pb1.x); sB[nxt][lr][kq + 5] = f2tf(pb1.y);
            sB[nxt][lr][kq + 6] = f2tf(pb1.z); sB[nxt][lr][kq + 7] = f2tf(pb1.w);
            __syncthreads();
        }
    }

    #pragma unroll
    for (int mm = 0; mm < 2; mm++)
    #pragma unroll
    for (int nn = 0; nn < 2; nn++) {
        int rr = row0 + wm + mm * 16 + fr;
        int cb = col0 + wn + nn * 8 + fc * 2;
        float2 v0 = { acc[mm][nn][0], acc[mm][nn][1] };
        float2 v1 = { acc[mm][nn][2], acc[mm][nn][3] };
        *(float2*)&C[(size_t)rr * H + cb] = v0;
        *(float2*)&C[(size_t)(rr + 8) * H + cb] = v1;
    }
}

// ---------------- PDL launch helper ----------------
template <typename F, typename... Args>
static inline void pdl_launch(F* func, dim3 grid, dim3 block, Args... args) {
    cudaLaunchConfig_t cfg = {};
    cfg.gridDim = grid;
    cfg.blockDim = block;
    cfg.dynamicSmemBytes = 0;
    cfg.stream = 0;    // legacy default stream (same as <<<>>>)
    cudaLaunchAttribute at[1];
    at[0].id = cudaLaunchAttributeProgrammaticStreamSerialization;
    at[0].val.programmaticStreamSerializationAllowed = 1;
    cfg.attrs = at;
    cfg.numAttrs = 1;
    cudaLaunchKernelEx(&cfg, func, args...);
}

// ---------------- launcher ----------------
extern "C" void kernel_launch(void* const* d_in, const int* in_sizes, int n_in,
                              void* d_out, int out_size) {
    const float* x     = (const float*)d_in[0];
    const void*  batch = d_in[1];
    const float* W_ih  = (const float*)d_in[2];
    const float* W_hh  = (const float*)d_in[3];
    const float* b_ih  = (const float*)d_in[4];
    const float* b_hh  = (const float*)d_in[5];
    const float* W_out = (const float*)d_in[6];
    const float* b_out = (const float*)d_in[7];
    float* out = (float*)d_out;
    int n = in_sizes[0] / H;
    int chunk = (n + CHB - 1) / CHB;

    prep_kernel<<<(G4 * K2H / 4 + 255) / 256, 256>>>(W_ih, W_hh, b_ih, b_hh, batch, n);

    // step 1: gates = bias (q_star = hs = 0)
    pdl_launch(lstm_first, dim3(NB), dim3(256), chunk);
    pdl_launch(attn_partial, dim3(CHB), dim3(256), x, n, chunk);

    // steps 2..3
    for (int s = 1; s < 3; s++) {
        pdl_launch(gemm_gates, dim3(G4 / 64, NB / 128, 2), dim3(256));
        pdl_launch(lstm_step, dim3(NB), dim3(256));
        pdl_launch(attn_partial, dim3(CHB), dim3(256), x, n, chunk);
    }

    pdl_launch(gemm_out, dim3(H / 64, NB / 64, 4), dim3(256), W_out);
    pdl_launch(out_epi, dim3(NB), dim3(256), b_out, out);
}

// round 14
// speedup vs baseline: 1.6628x; 1.0279x over previous
#include <cuda_runtime.h>
#include <math.h>

#define H      256
#define NB     512      // n_graphs
#define G4     1024     // 4*H
#define K2H    512      // 2*H
#define CHB    608      // attention chunk blocks (4 per SM x 152)
#define MAXP   8        // max partials per graph (<=3 actually occur)

// ---------------- device scratch (no allocation allowed) ----------------
__device__ __align__(16) float g_Wc[G4 * K2H];     // combined gate weight [1024][512]
__device__ __align__(16) float g_bias[G4];         // b_ih + b_hh
__device__ __align__(16) float g_hs[NB * H];
__device__ __align__(16) float g_cs[NB * H];
__device__ __align__(16) float g_qstar[NB * K2H];  // [hs, r]
__device__ __align__(16) float g_gates4[4 * NB * G4]; // split-K=4 partial gates
__device__ __align__(16) float g_out4[4 * NB * H];    // split-K=4 partial out
__device__ int   g_seg[NB + 1];
__device__ int   g_cnt[NB];                        // partial slot counters
__device__ int   g_done[NB];                       // completed-partials counters
__device__ int   g_exp[NB];                        // expected partials per graph
__device__ float g_pm[NB * MAXP];                  // partial max
__device__ float g_pd[NB * MAXP];                  // partial denom (rel. to pm)
__device__ __align__(16) float g_pr[NB * MAXP * H];// partial weighted sum (rel. to pm)

__device__ __forceinline__ void dep_sync() {
#if __CUDA_ARCH__ >= 900
    cudaGridDependencySynchronize();
#endif
}

// ---------------- prep: Wcomb = [W_ih[:,:H]+W_hh | W_ih[:,H:]], bias, seg starts ----------------
__global__ void prep_kernel(const float* __restrict__ W_ih, const float* __restrict__ W_hh,
                            const float* __restrict__ b_ih, const float* __restrict__ b_hh,
                            const void* __restrict__ batch_raw, int n) {
    int i = blockIdx.x * blockDim.x + threadIdx.x;   // over G4*K2H/4 = 131072
    if (i < G4 * K2H / 4) {
        int j = i >> 7;              // row (gate index)
        int k4 = (i & 127) * 4;      // col (4-aligned)
        float4 v = *(const float4*)&W_ih[i * 4];
        if (k4 < H) {
            float4 w = *(const float4*)&W_hh[j * H + k4];
            v.x += w.x; v.y += w.y; v.z += w.z; v.w += w.w;
        }
        *(float4*)&g_Wc[i * 4] = v;
    }
    if (i < G4) g_bias[i] = b_ih[i] + b_hh[i];
    if (i <= NB) {
        // lower_bound(i) over sorted batch; dtype-agnostic (int32 vs int64)
        const int* b32 = (const int*)batch_raw;
        bool is64 = (b32[n - 1] == 0);   // int64 view: high word of last elem (<512)
        int lo = 0, hi = n;
        if (is64) {
            const long long* b64 = (const long long*)batch_raw;
            long long gv = (long long)i;
            while (lo < hi) { int mid = (lo + hi) >> 1; if (b64[mid] < gv) lo = mid + 1; else hi = mid; }
        } else {
            while (lo < hi) { int mid = (lo + hi) >> 1; if (b32[mid] < i) lo = mid + 1; else hi = mid; }
        }
        g_seg[i] = lo;
    }
}

__device__ __forceinline__ float sigf(float v) { return 1.0f / (1.0f + __expf(-v)); }

// ---------------- LSTM step 1: q_star = hs = 0 -> gates = bias only ----------------
__global__ void lstm_first(int chunk) {
    dep_sync();
    int idx = blockIdx.x * blockDim.x + threadIdx.x;   // NB*H
    int g = idx >> 8;
    int t = idx & (H - 1);
    if (t == 0) {
        int s = g_seg[g], e = g_seg[g + 1];
        g_exp[g] = (e > s) ? ((e - 1) / chunk - s / chunk + 1) : 0;
    }
    float ig = g_bias[t], gg = g_bias[2 * H + t], og = g_bias[3 * H + t];
    float c = sigf(ig) * tanhf(gg);        // f-gate * cs(=0) drops out
    float h = sigf(og) * tanhf(c);
    g_cs[idx] = c;
    g_hs[idx] = h;
    g_qstar[g * K2H + t]     = h;          // q half
    g_qstar[g * K2H + H + t] = 0.f;        // r half (combine overwrites; stays 0 if empty graph)
}

// ---------------- LSTM steps 2..: sum split-K=4 gate partials + bias ----------------
__global__ void lstm_step() {
    dep_sync();
    int idx = blockIdx.x * blockDim.x + threadIdx.x;   // NB*H
    int g = idx >> 8;
    int t = idx & (H - 1);
    const float* gr0 = g_gates4 + g * G4;
    const float* gr1 = gr0 + NB * G4;
    const float* gr2 = gr1 + NB * G4;
    const float* gr3 = gr2 + NB * G4;
    float ig = gr0[t]         + gr1[t]         + gr2[t]         + gr3[t]         + g_bias[t];
    float fg = gr0[H + t]     + gr1[H + t]     + gr2[H + t]     + gr3[H + t]     + g_bias[H + t];
    float gg = gr0[2 * H + t] + gr1[2 * H + t] + gr2[2 * H + t] + gr3[2 * H + t] + g_bias[2 * H + t];
    float og = gr0[3 * H + t] + gr1[3 * H + t] + gr2[3 * H + t] + gr3[3 * H + t] + g_bias[3 * H + t];
    float c = sigf(fg) * g_cs[idx] + sigf(ig) * tanhf(gg);
    float h = sigf(og) * tanhf(c);
    g_cs[idx] = c;
    g_hs[idx] = h;
    g_qstar[g * K2H + t]     = h;
    g_qstar[g * K2H + H + t] = 0.f;
}

// ---------------- out epilogue: sum 4 split-K partials + bias ----------------
__global__ void out_epi(const float* __restrict__ b_out, float* __restrict__ out) {
    dep_sync();
    int idx = blockIdx.x * blockDim.x + threadIdx.x;   // NB*H
    int t = idx & (H - 1);
    out[idx] = g_out4[idx] + g_out4[NB * H + idx]
             + g_out4[2 * NB * H + idx] + g_out4[3 * NB * H + idx] + b_out[t];
}

// ---------------- balanced attention: equal node chunks -> partials; last block combines ----------------
__global__ __launch_bounds__(256, 4) void attn_partial(const float* __restrict__ x, int n, int chunk) {
    int c0 = blockIdx.x * chunk;
    if (c0 >= n) return;
    dep_sync();
    int c1 = min(n, c0 + chunk);
    int warp = threadIdx.x >> 5, lane = threadIdx.x & 31;
    int t = threadIdx.x;

    // find g with seg[g] <= c0 < seg[g+1] (max g with seg[g] <= c0)
    int lo = 0, hi = NB - 1;
    while (lo < hi) { int mid = (lo + hi + 1) >> 1; if (g_seg[mid] <= c0) lo = mid; else hi = mid - 1; }
    int g = lo;

    __shared__ float sm_m[8], sm_d[8];
    __shared__ float sm_r[8][H];
    __shared__ int sm_slot;
    __shared__ int sm_last;

    while (c0 < c1) {
        int segend = g_seg[g + 1];
        int e = min(segend, c1);
        if (e > c0) {
            const float4* qv = reinterpret_cast<const float4*>(g_hs + g * H);
            float4 q0 = qv[lane * 2];
            float4 q1 = qv[lane * 2 + 1];

            float m = -3.0e38f, d = 0.0f;
            float r0 = 0.f, r1 = 0.f, r2 = 0.f, r3 = 0.f, r4 = 0.f, r5 = 0.f, r6 = 0.f, r7 = 0.f;

            int i = c0 + warp * 2;
            for (; i + 1 < e; i += 16) {
                const float4* xv0 = reinterpret_cast<const float4*>(x + (size_t)i * H);
                const float4* xv1 = reinterpret_cast<const float4*>(x + (size_t)(i + 1) * H);
                float4 a0 = xv0[lane * 2];
                float4 b0 = xv0[lane * 2 + 1];
                float4 a1 = xv1[lane * 2];
                float4 b1 = xv1[lane * 2 + 1];

                float p0 = a0.x * q0.x + a0.y * q0.y + a0.z * q0.z + a0.w * q0.w
                         + b0.x * q1.x + b0.y * q1.y + b0.z * q1.z + b0.w * q1.w;
                float p1 = a1.x * q0.x + a1.y * q0.y + a1.z * q0.z + a1.w * q0.w
                         + b1.x * q1.x + b1.y * q1.y + b1.z * q1.z + b1.w * q1.w;
                #pragma unroll
                for (int o = 16; o > 0; o >>= 1) {
                    p0 += __shfl_xor_sync(0xffffffffu, p0, o);
                    p1 += __shfl_xor_sync(0xffffffffu, p1, o);
                }
                if (p0 > m) {
                    float f = __expf(m - p0);
                    d *= f; r0 *= f; r1 *= f; r2 *= f; r3 *= f; r4 *= f; r5 *= f; r6 *= f; r7 *= f;
                    m = p0;
                }
                float w = __expf(p0 - m);
                d += w;
                r0 = fmaf(w, a0.x, r0); r1 = fmaf(w, a0.y, r1);
                r2 = fmaf(w, a0.z, r2); r3 = fmaf(w, a0.w, r3);
                r4 = fmaf(w, b0.x, r4); r5 = fmaf(w, b0.y, r5);
                r6 = fmaf(w, b0.z, r6); r7 = fmaf(w, b0.w, r7);
                if (p1 > m) {
                    float f = __expf(m - p1);
                    d *= f; r0 *= f; r1 *= f; r2 *= f; r3 *= f; r4 *= f; r5 *= f; r6 *= f; r7 *= f;
                    m = p1;
                }
                w = __expf(p1 - m);
                d += w;
                r0 = fmaf(w, a1.x, r0); r1 = fmaf(w, a1.y, r1);
                r2 = fmaf(w, a1.z, r2); r3 = fmaf(w, a1.w, r3);
                r4 = fmaf(w, b1.x, r4); r5 = fmaf(w, b1.y, r5);
                r6 = fmaf(w, b1.z, r6); r7 = fmaf(w, b1.w, r7);
            }
            if (i < e) {
                const float4* xv0 = reinterpret_cast<const float4*>(x + (size_t)i * H);
                float4 a0 = xv0[lane * 2];
                float4 b0 = xv0[lane * 2 + 1];
                float p0 = a0.x * q0.x + a0.y * q0.y + a0.z * q0.z + a0.w * q0.w
                         + b0.x * q1.x + b0.y * q1.y + b0.z * q1.z + b0.w * q1.w;
                #pragma unroll
                for (int o = 16; o > 0; o >>= 1) p0 += __shfl_xor_sync(0xffffffffu, p0, o);
                if (p0 > m) {
                    float f = __expf(m - p0);
                    d *= f; r0 *= f; r1 *= f; r2 *= f; r3 *= f; r4 *= f; r5 *= f; r6 *= f; r7 *= f;
                    m = p0;
                }
                float w = __expf(p0 - m);
                d += w;
                r0 = fmaf(w, a0.x, r0); r1 = fmaf(w, a0.y, r1);
                r2 = fmaf(w, a0.z, r2); r3 = fmaf(w, a0.w, r3);
                r4 = fmaf(w, b0.x, r4); r5 = fmaf(w, b0.y, r5);
                r6 = fmaf(w, b0.z, r6); r7 = fmaf(w, b0.w, r7);
            }

            // block-level merge of 8 warps
            if (lane == 0) { sm_m[warp] = m; sm_d[warp] = d; }
            __syncthreads();
            float M = sm_m[0];
            #pragma unroll
            for (int w = 1; w < 8; w++) M = fmaxf(M, sm_m[w]);
            float D = 0.f;
            #pragma unroll
            for (int w = 0; w < 8; w++) D += sm_d[w] * __expf(sm_m[w] - M);

            float sc = __expf(m - M);   // 0 for warps with no nodes
            int base = lane * 8;
            sm_r[warp][base + 0] = r0 * sc; sm_r[warp][base + 1] = r1 * sc;
            sm_r[warp][base + 2] = r2 * sc; sm_r[warp][base + 3] = r3 * sc;
            sm_r[warp][base + 4] = r4 * sc; sm_r[warp][base + 5] = r5 * sc;
            sm_r[warp][base + 6] = r6 * sc; sm_r[warp][base + 7] = r7 * sc;
            if (t == 0) sm_slot = atomicAdd(&g_cnt[g], 1);
            __syncthreads();

            float R = 0.f;
            #pragma unroll
            for (int w = 0; w < 8; w++) R += sm_r[w][t];
            int p = g * MAXP + sm_slot;
            g_pr[(size_t)p * H + t] = R;              // unnormalized, relative to M
            if (t == 0) { g_pm[p] = M; g_pd[p] = D; }

            // last-block-done combine
            __threadfence();
            __syncthreads();
            if (t == 0) sm_last = (atomicAdd(&g_done[g], 1) + 1 == g_exp[g]) ? 1 : 0;
            __syncthreads();
            if (sm_last) {
                __threadfence();
                int cnt = g_exp[g];
                float M2 = -3.0e38f;
                for (int pp = 0; pp < cnt; pp++) M2 = fmaxf(M2, g_pm[g * MAXP + pp]);
                float D2 = 0.f, R2 = 0.f;
                for (int pp = 0; pp < cnt; pp++) {
                    float f = __expf(g_pm[g * MAXP + pp] - M2);
                    D2 += g_pd[g * MAXP + pp] * f;
                    R2 += g_pr[(size_t)(g * MAXP + pp) * H + t] * f;
                }
                R2 = (D2 > 0.f) ? (R2 / D2) : 0.f;
                g_qstar[g * K2H + H + t] = R2;        // r half (q half written by lstm)
                if (t == 0) { g_cnt[g] = 0; g_done[g] = 0; }
            }
            __syncthreads();   // protect smem reuse for next sub-segment
            c0 = e;
        }
        if (e == segend) g++;
    }
}

// ---------------- tf32 tensor-core NT GEMM helpers ----------------
__device__ __forceinline__ unsigned f2tf(float f) {
    unsigned r; asm("cvt.rna.tf32.f32 %0, %1;" : "=r"(r) : "f"(f)); return r;
}
__device__ __forceinline__ void mma_tf32(float* d, const unsigned* a, const unsigned* b) {
    asm volatile("mma.sync.aligned.m16n8k8.row.col.f32.tf32.tf32.f32 "
        "{%0,%1,%2,%3}, {%4,%5,%6,%7}, {%8,%9}, {%0,%1,%2,%3};"
        : "+f"(d[0]), "+f"(d[1]), "+f"(d[2]), "+f"(d[3])
        : "r"(a[0]), "r"(a[1]), "r"(a[2]), "r"(a[3]), "r"(b[0]), "r"(b[1]));
}

// 64x64 output tile, 256 thr (8 warps 2Mx4N; warp tile 32x16), BK=32,
// double-buffered smem. Computes partial C (no bias) over [kbase, kbase+nsteps*32).
__device__ __forceinline__ void gemm_mma64_body(const float* __restrict__ A,
                                                const float* __restrict__ Bm,
                                                float* __restrict__ C, int Ndim,
                                                int kbase, int nsteps) {
    __shared__ unsigned sA[2][64][36];   // stride 36 -> conflict-light frag loads
    __shared__ unsigned sB[2][64][36];
    int tid = threadIdx.x;
    int lane = tid & 31, warp = tid >> 5;
    int wm = (warp & 1) * 32, wn = (warp >> 1) * 16;
    int row0 = blockIdx.y * 64, col0 = blockIdx.x * 64;
    int lr = tid >> 2, kq = (tid & 3) * 8;
    int fr = lane >> 2, fc = lane & 3;

    const float* Apf = A + (size_t)(row0 + lr) * K2H + kbase + kq;
    const float* Bpf = Bm + (size_t)(col0 + lr) * K2H + kbase + kq;

    // fill buffer 0 with chunk 0
    {
        float4 a0 = *(const float4*)Apf;
        float4 a1 = *(const float4*)(Apf + 4);
        float4 b0 = *(const float4*)Bpf;
        float4 b1 = *(const float4*)(Bpf + 4);
        sA[0][lr][kq + 0] = f2tf(a0.x); sA[0][lr][kq + 1] = f2tf(a0.y);
        sA[0][lr][kq + 2] = f2tf(a0.z); sA[0][lr][kq + 3] = f2tf(a0.w);
        sA[0][lr][kq + 4] = f2tf(a1.x); sA[0][lr][kq + 5] = f2tf(a1.y);
        sA[0][lr][kq + 6] = f2tf(a1.z); sA[0][lr][kq + 7] = f2tf(a1.w);
        sB[0][lr][kq + 0] = f2tf(b0.x); sB[0][lr][kq + 1] = f2tf(b0.y);
        sB[0][lr][kq + 2] = f2tf(b0.z); sB[0][lr][kq + 3] = f2tf(b0.w);
        sB[0][lr][kq + 4] = f2tf(b1.x); sB[0][lr][kq + 5] = f2tf(b1.y);
        sB[0][lr][kq + 6] = f2tf(b1.z); sB[0][lr][kq + 7] = f2tf(b1.w);
    }
    __syncthreads();

    float acc[2][2][4] = {};
    float4 pa0, pa1, pb0, pb1;

    for (int s = 0; s < nsteps; s++) {
        int cur = s & 1, nxt = 1 - cur;
        if (s + 1 < nsteps) {   // global prefetch before the MMA burst
            int off = (s + 1) * 32;
            pa0 = *(const float4*)(Apf + off);
            pa1 = *(const float4*)(Apf + off + 4);
            pb0 = *(const float4*)(Bpf + off);
            pb1 = *(const float4*)(Bpf + off + 4);
        }

        #pragma unroll
        for (int ks = 0; ks < 4; ks++) {
            int kc = ks * 8 + fc;
            unsigned a0[4] = { sA[cur][wm + fr][kc],      sA[cur][wm + fr + 8][kc],
                               sA[cur][wm + fr][kc + 4],  sA[cur][wm + fr + 8][kc + 4] };
            unsigned a1[4] = { sA[cur][wm + 16 + fr][kc],     sA[cur][wm + 24 + fr][kc],
                               sA[cur][wm + 16 + fr][kc + 4], sA[cur][wm + 24 + fr][kc + 4] };
            unsigned b0[2] = { sB[cur][wn + fr][kc], sB[cur][wn + fr][kc + 4] };
            unsigned b1[2] = { sB[cur][wn + 8 + fr][kc], sB[cur][wn + 8 + fr][kc + 4] };
            mma_tf32(acc[0][0], a0, b0);
            mma_tf32(acc[0][1], a0, b1);
            mma_tf32(acc[1][0], a1, b0);
            mma_tf32(acc[1][1], a1, b1);
        }

        if (s + 1 < nsteps) {   // stage next chunk into the other buffer
            sA[nxt][lr][kq + 0] = f2tf(pa0.x); sA[nxt][lr][kq + 1] = f2tf(pa0.y);
            sA[nxt][lr][kq + 2] = f2tf(pa0.z); sA[nxt][lr][kq + 3] = f2tf(pa0.w);
            sA[nxt][lr][kq + 4] = f2tf(pa1.x); sA[nxt][lr][kq + 5] = f2tf(pa1.y);
            sA[nxt][lr][kq + 6] = f2tf(pa1.z); sA[nxt][lr][kq + 7] = f2tf(pa1.w);
            sB[nxt][lr][kq + 0] = f2tf(pb0.x); sB[nxt][lr][kq + 1] = f2tf(pb0.y);
            sB[nxt][lr][kq + 2] = f2tf(pb0.z); sB[nxt][lr][kq + 3] = f2tf(pb0.w);
            sB[nxt][lr][kq + 4] = f2tf(pb1.x); sB[nxt][lr][kq + 5] = f2tf(pb1.y);
            sB[nxt][lr][kq + 6] = f2tf(pb1.z); sB[nxt][lr][kq + 7] = f2tf(pb1.w);
            __syncthreads();
        }
    }

    #pragma unroll
    for (int mm = 0; mm < 2; mm++)
    #pragma unroll
    for (int nn = 0; nn < 2; nn++) {
        int rr = row0 + wm + mm * 16 + fr;
        int cb = col0 + wn + nn * 8 + fc * 2;
        float2 v0 = { acc[mm][nn][0], acc[mm][nn][1] };
        float2 v1 = { acc[mm][nn][2], acc[mm][nn][3] };
        *(float2*)&C[(size_t)rr * Ndim + cb] = v0;
        *(float2*)&C[(size_t)(rr + 8) * Ndim + cb] = v1;
    }
}

__global__ __launch_bounds__(256) void gemm_gates() {
    // split-K=4: partial gates[z][512][1024] over K quarter z; grid (16, 8, 4) = 512 blocks
    int z = blockIdx.z;
    dep_sync();
    gemm_mma64_body(g_qstar, g_Wc, g_gates4 + (size_t)z * NB * G4, G4, z * 128, 4);
}

__global__ __launch_bounds__(256) void gemm_out(const float* __restrict__ W_out) {
    // split-K=4: partial out[z][512][256] over K quarter z; grid (4, 8, 4) = 128 blocks
    int z = blockIdx.z;
    dep_sync();
    gemm_mma64_body(g_qstar, W_out, g_out4 + (size_t)z * NB * H, H, z * 128, 4);
}

// ---------------- PDL launch helper ----------------
template <typename F, typename... Args>
static inline void pdl_launch(F* func, dim3 grid, dim3 block, Args... args) {
    cudaLaunchConfig_t cfg = {};
    cfg.gridDim = grid;
    cfg.blockDim = block;
    cfg.dynamicSmemBytes = 0;
    cfg.stream = 0;    // legacy default stream (same as <<<>>>)
    cudaLaunchAttribute at[1];
    at[0].id = cudaLaunchAttributeProgrammaticStreamSerialization;
    at[0].val.programmaticStreamSerializationAllowed = 1;
    cfg.attrs = at;
    cfg.numAttrs = 1;
    cudaLaunchKernelEx(&cfg, func, args...);
}

// ---------------- launcher ----------------
extern "C" void kernel_launch(void* const* d_in, const int* in_sizes, int n_in,
                              void* d_out, int out_size) {
    const float* x     = (const float*)d_in[0];
    const void*  batch = d_in[1];
    const float* W_ih  = (const float*)d_in[2];
    const float* W_hh  = (const float*)d_in[3];
    const float* b_ih  = (const float*)d_in[4];
    const float* b_hh  = (const float*)d_in[5];
    const float* W_out = (const float*)d_in[6];
    const float* b_out = (const float*)d_in[7];
    float* out = (float*)d_out;
    int n = in_sizes[0] / H;
    int chunk = (n + CHB - 1) / CHB;

    prep_kernel<<<(G4 * K2H / 4 + 255) / 256, 256>>>(W_ih, W_hh, b_ih, b_hh, batch, n);

    // step 1: gates = bias (q_star = hs = 0)
    pdl_launch(lstm_first, dim3(NB), dim3(256), chunk);
    pdl_launch(attn_partial, dim3(CHB), dim3(256), x, n, chunk);

    // steps 2..3
    for (int s = 1; s < 3; s++) {
        pdl_launch(gemm_gates, dim3(G4 / 64, NB / 64, 4), dim3(256));
        pdl_launch(lstm_step, dim3(NB), dim3(256));
        pdl_launch(attn_partial, dim3(CHB), dim3(256), x, n, chunk);
    }

    pdl_launch(gemm_out, dim3(H / 64, NB / 64, 4), dim3(256), W_out);
    pdl_launch(out_epi, dim3(NB), dim3(256), b_out, out);
}

// round 15
// speedup vs baseline: 1.7186x; 1.0336x over previous
#include <cuda_runtime.h>
#include <cuda_fp16.h>
#include <math.h>

#define H      256
#define NB     512      // n_graphs
#define G4     1024     // 4*H
#define K2H    512      // 2*H
#define CHB    608      // attention chunk blocks (4 per SM x 152)
#define MAXP   8        // max partials per graph (<=3 actually occur)
#define MAXN   204800   // fp16 x-cache capacity (nodes)

// ---------------- device scratch (no allocation allowed) ----------------
__device__ __align__(16) float g_Wc[G4 * K2H];     // combined gate weight [1024][512]
__device__ __align__(16) float g_bias[G4];         // b_ih + b_hh
__device__ __align__(16) float g_hs[NB * H];
__device__ __align__(16) float g_cs[NB * H];
__device__ __align__(16) float g_qstar[NB * K2H];  // [hs, r]
__device__ __align__(16) float g_gates4[4 * NB * G4]; // split-K=4 partial gates
__device__ __align__(16) float g_out4[4 * NB * H];    // split-K=4 partial out
__device__ __align__(16) __half g_x16[(size_t)MAXN * H]; // fp16 cache of x
__device__ int   g_seg[NB + 1];
__device__ int   g_cnt[NB];                        // partial slot counters
__device__ int   g_done[NB];                       // completed-partials counters
__device__ int   g_exp[NB];                        // expected partials per graph
__device__ float g_pm[NB * MAXP];                  // partial max
__device__ float g_pd[NB * MAXP];                  // partial denom (rel. to pm)
__device__ __align__(16) float g_pr[NB * MAXP * H];// partial weighted sum (rel. to pm)

__device__ __forceinline__ void dep_sync() {
#if __CUDA_ARCH__ >= 900
    cudaGridDependencySynchronize();
#endif
}

// ---------------- prep: Wcomb = [W_ih[:,:H]+W_hh | W_ih[:,H:]], bias, seg starts ----------------
__global__ void prep_kernel(const float* __restrict__ W_ih, const float* __restrict__ W_hh,
                            const float* __restrict__ b_ih, const float* __restrict__ b_hh,
                            const void* __restrict__ batch_raw, int n) {
    int i = blockIdx.x * blockDim.x + threadIdx.x;   // over G4*K2H/4 = 131072
    if (i < G4 * K2H / 4) {
        int j = i >> 7;              // row (gate index)
        int k4 = (i & 127) * 4;      // col (4-aligned)
        float4 v = *(const float4*)&W_ih[i * 4];
        if (k4 < H) {
            float4 w = *(const float4*)&W_hh[j * H + k4];
            v.x += w.x; v.y += w.y; v.z += w.z; v.w += w.w;
        }
        *(float4*)&g_Wc[i * 4] = v;
    }
    if (i < G4) g_bias[i] = b_ih[i] + b_hh[i];
    if (i <= NB) {
        // lower_bound(i) over sorted batch; dtype-agnostic (int32 vs int64)
        const int* b32 = (const int*)batch_raw;
        bool is64 = (b32[n - 1] == 0);   // int64 view: high word of last elem (<512)
        int lo = 0, hi = n;
        if (is64) {
            const long long* b64 = (const long long*)batch_raw;
            long long gv = (long long)i;
            while (lo < hi) { int mid = (lo + hi) >> 1; if (b64[mid] < gv) lo = mid + 1; else hi = mid; }
        } else {
            while (lo < hi) { int mid = (lo + hi) >> 1; if (b32[mid] < i) lo = mid + 1; else hi = mid; }
        }
        g_seg[i] = lo;
    }
}

__device__ __forceinline__ float sigf(float v) { return 1.0f / (1.0f + __expf(-v)); }

// ---------------- LSTM step 1: q_star = hs = 0 -> gates = bias only ----------------
__global__ void lstm_first(int chunk) {
    dep_sync();
    int idx = blockIdx.x * blockDim.x + threadIdx.x;   // NB*H
    int g = idx >> 8;
    int t = idx & (H - 1);
    if (t == 0) {
        int s = g_seg[g], e = g_seg[g + 1];
        g_exp[g] = (e > s) ? ((e - 1) / chunk - s / chunk + 1) : 0;
    }
    float ig = g_bias[t], gg = g_bias[2 * H + t], og = g_bias[3 * H + t];
    float c = sigf(ig) * tanhf(gg);        // f-gate * cs(=0) drops out
    float h = sigf(og) * tanhf(c);
    g_cs[idx] = c;
    g_hs[idx] = h;
    g_qstar[g * K2H + t]     = h;          // q half
    g_qstar[g * K2H + H + t] = 0.f;        // r half (combine overwrites; stays 0 if empty graph)
}

// ---------------- LSTM steps 2..: sum split-K=4 gate partials + bias ----------------
__global__ void lstm_step() {
    dep_sync();
    int idx = blockIdx.x * blockDim.x + threadIdx.x;   // NB*H
    int g = idx >> 8;
    int t = idx & (H - 1);
    const float* gr0 = g_gates4 + g * G4;
    const float* gr1 = gr0 + NB * G4;
    const float* gr2 = gr1 + NB * G4;
    const float* gr3 = gr2 + NB * G4;
    float ig = gr0[t]         + gr1[t]         + gr2[t]         + gr3[t]         + g_bias[t];
    float fg = gr0[H + t]     + gr1[H + t]     + gr2[H + t]     + gr3[H + t]     + g_bias[H + t];
    float gg = gr0[2 * H + t] + gr1[2 * H + t] + gr2[2 * H + t] + gr3[2 * H + t] + g_bias[2 * H + t];
    float og = gr0[3 * H + t] + gr1[3 * H + t] + gr2[3 * H + t] + gr3[3 * H + t] + g_bias[3 * H + t];
    float c = sigf(fg) * g_cs[idx] + sigf(ig) * tanhf(gg);
    float h = sigf(og) * tanhf(c);
    g_cs[idx] = c;
    g_hs[idx] = h;
    g_qstar[g * K2H + t]     = h;
    g_qstar[g * K2H + H + t] = 0.f;
}

// ---------------- out epilogue: sum 4 split-K partials + bias ----------------
__global__ void out_epi(const float* __restrict__ b_out, float* __restrict__ out) {
    dep_sync();
    int idx = blockIdx.x * blockDim.x + threadIdx.x;   // NB*H
    int t = idx & (H - 1);
    out[idx] = g_out4[idx] + g_out4[NB * H + idx]
             + g_out4[2 * NB * H + idx] + g_out4[3 * NB * H + idx] + b_out[t];
}

// ---------------- fp16 pack/unpack helpers ----------------
__device__ __forceinline__ uint4 f2h8(float4 a, float4 b) {
    uint4 h;
    __half2 t;
    t = __float22half2_rn(make_float2(a.x, a.y)); h.x = *(unsigned*)&t;
    t = __float22half2_rn(make_float2(a.z, a.w)); h.y = *(unsigned*)&t;
    t = __float22half2_rn(make_float2(b.x, b.y)); h.z = *(unsigned*)&t;
    t = __float22half2_rn(make_float2(b.z, b.w)); h.w = *(unsigned*)&t;
    return h;
}
__device__ __forceinline__ void h2f8(uint4 h, float4& a, float4& b) {
    float2 f;
    f = __half22float2(*(__half2*)&h.x); a.x = f.x; a.y = f.y;
    f = __half22float2(*(__half2*)&h.y); a.z = f.x; a.w = f.y;
    f = __half22float2(*(__half2*)&h.z); b.x = f.x; b.y = f.y;
    f = __half22float2(*(__half2*)&h.w); b.z = f.x; b.w = f.y;
}

// ---------------- balanced attention: equal node chunks -> partials; last block combines ----
// MODE 0: read fp32 x, also write fp16 cache. MODE 1: read fp16 cache. MODE 2: fp32 only.
template <int MODE>
__device__ __forceinline__ void attn_body(const float* __restrict__ x, int n, int chunk) {
    int c0 = blockIdx.x * chunk;
    if (c0 >= n) return;
    dep_sync();
    int c1 = min(n, c0 + chunk);
    int warp = threadIdx.x >> 5, lane = threadIdx.x & 31;
    int t = threadIdx.x;

    // find g with seg[g] <= c0 < seg[g+1] (max g with seg[g] <= c0)
    int lo = 0, hi = NB - 1;
    while (lo < hi) { int mid = (lo + hi + 1) >> 1; if (g_seg[mid] <= c0) lo = mid; else hi = mid - 1; }
    int g = lo;

    __shared__ float sm_m[8], sm_d[8];
    __shared__ float sm_r[8][H];
    __shared__ int sm_slot;
    __shared__ int sm_last;

    while (c0 < c1) {
        int segend = g_seg[g + 1];
        int e = min(segend, c1);
        if (e > c0) {
            const float4* qv = reinterpret_cast<const float4*>(g_hs + g * H);
            float4 q0 = qv[lane * 2];
            float4 q1 = qv[lane * 2 + 1];

            float m = -3.0e38f, d = 0.0f;
            float r0 = 0.f, r1 = 0.f, r2 = 0.f, r3 = 0.f, r4 = 0.f, r5 = 0.f, r6 = 0.f, r7 = 0.f;

            int i = c0 + warp * 2;
            for (; i + 1 < e; i += 16) {
                float4 a0, b0, a1, b1;
                if (MODE == 1) {
                    uint4 h0 = *((const uint4*)(g_x16 + (size_t)i * H) + lane);
                    uint4 h1 = *((const uint4*)(g_x16 + (size_t)(i + 1) * H) + lane);
                    h2f8(h0, a0, b0);
                    h2f8(h1, a1, b1);
                } else {
                    const float4* xv0 = reinterpret_cast<const float4*>(x + (size_t)i * H);
                    const float4* xv1 = reinterpret_cast<const float4*>(x + (size_t)(i + 1) * H);
                    a0 = xv0[lane * 2];
                    b0 = xv0[lane * 2 + 1];
                    a1 = xv1[lane * 2];
                    b1 = xv1[lane * 2 + 1];
                    if (MODE == 0) {
                        *((uint4*)(g_x16 + (size_t)i * H) + lane)       = f2h8(a0, b0);
                        *((uint4*)(g_x16 + (size_t)(i + 1) * H) + lane) = f2h8(a1, b1);
                    }
                }

                float p0 = a0.x * q0.x + a0.y * q0.y + a0.z * q0.z + a0.w * q0.w
                         + b0.x * q1.x + b0.y * q1.y + b0.z * q1.z + b0.w * q1.w;
                float p1 = a1.x * q0.x + a1.y * q0.y + a1.z * q0.z + a1.w * q0.w
                         + b1.x * q1.x + b1.y * q1.y + b1.z * q1.z + b1.w * q1.w;
                #pragma unroll
                for (int o = 16; o > 0; o >>= 1) {
                    p0 += __shfl_xor_sync(0xffffffffu, p0, o);
                    p1 += __shfl_xor_sync(0xffffffffu, p1, o);
                }
                if (p0 > m) {
                    float f = __expf(m - p0);
                    d *= f; r0 *= f; r1 *= f; r2 *= f; r3 *= f; r4 *= f; r5 *= f; r6 *= f; r7 *= f;
                    m = p0;
                }
                float w = __expf(p0 - m);
                d += w;
                r0 = fmaf(w, a0.x, r0); r1 = fmaf(w, a0.y, r1);
                r2 = fmaf(w, a0.z, r2); r3 = fmaf(w, a0.w, r3);
                r4 = fmaf(w, b0.x, r4); r5 = fmaf(w, b0.y, r5);
                r6 = fmaf(w, b0.z, r6); r7 = fmaf(w, b0.w, r7);
                if (p1 > m) {
                    float f = __expf(m - p1);
                    d *= f; r0 *= f; r1 *= f; r2 *= f; r3 *= f; r4 *= f; r5 *= f; r6 *= f; r7 *= f;
                    m = p1;
                }
                w = __expf(p1 - m);
                d += w;
                r0 = fmaf(w, a1.x, r0); r1 = fmaf(w, a1.y, r1);
                r2 = fmaf(w, a1.z, r2); r3 = fmaf(w, a1.w, r3);
                r4 = fmaf(w, b1.x, r4); r5 = fmaf(w, b1.y, r5);
                r6 = fmaf(w, b1.z, r6); r7 = fmaf(w, b1.w, r7);
            }
            if (i < e) {
                float4 a0, b0;
                if (MODE == 1) {
                    uint4 h0 = *((const uint4*)(g_x16 + (size_t)i * H) + lane);
                    h2f8(h0, a0, b0);
                } else {
                    const float4* xv0 = reinterpret_cast<const float4*>(x + (size_t)i * H);
                    a0 = xv0[lane * 2];
                    b0 = xv0[lane * 2 + 1];
                    if (MODE == 0)
                        *((uint4*)(g_x16 + (size_t)i * H) + lane) = f2h8(a0, b0);
                }
                float p0 = a0.x * q0.x + a0.y * q0.y + a0.z * q0.z + a0.w * q0.w
                         + b0.x * q1.x + b0.y * q1.y + b0.z * q1.z + b0.w * q1.w;
                #pragma unroll
                for (int o = 16; o > 0; o >>= 1) p0 += __shfl_xor_sync(0xffffffffu, p0, o);
                if (p0 > m) {
                    float f = __expf(m - p0);
                    d *= f; r0 *= f; r1 *= f; r2 *= f; r3 *= f; r4 *= f; r5 *= f; r6 *= f; r7 *= f;
                    m = p0;
                }
                float w = __expf(p0 - m);
                d += w;
                r0 = fmaf(w, a0.x, r0); r1 = fmaf(w, a0.y, r1);
                r2 = fmaf(w, a0.z, r2); r3 = fmaf(w, a0.w, r3);
                r4 = fmaf(w, b0.x, r4); r5 = fmaf(w, b0.y, r5);
                r6 = fmaf(w, b0.z, r6); r7 = fmaf(w, b0.w, r7);
            }

            // block-level merge of 8 warps
            if (lane == 0) { sm_m[warp] = m; sm_d[warp] = d; }
            __syncthreads();
            float M = sm_m[0];
            #pragma unroll
            for (int w = 1; w < 8; w++) M = fmaxf(M, sm_m[w]);
            float D = 0.f;
            #pragma unroll
            for (int w = 0; w < 8; w++) D += sm_d[w] * __expf(sm_m[w] - M);

            float sc = __expf(m - M);   // 0 for warps with no nodes
            int base = lane * 8;
            sm_r[warp][base + 0] = r0 * sc; sm_r[warp][base + 1] = r1 * sc;
            sm_r[warp][base + 2] = r2 * sc; sm_r[warp][base + 3] = r3 * sc;
            sm_r[warp][base + 4] = r4 * sc; sm_r[warp][base + 5] = r5 * sc;
            sm_r[warp][base + 6] = r6 * sc; sm_r[warp][base + 7] = r7 * sc;
            if (t == 0) sm_slot = atomicAdd(&g_cnt[g], 1);
            __syncthreads();

            float R = 0.f;
            #pragma unroll
            for (int w = 0; w < 8; w++) R += sm_r[w][t];
            int p = g * MAXP + sm_slot;
            g_pr[(size_t)p * H + t] = R;              // unnormalized, relative to M
            if (t == 0) { g_pm[p] = M; g_pd[p] = D; }

            // last-block-done combine
            __threadfence();
            __syncthreads();
            if (t == 0) sm_last = (atomicAdd(&g_done[g], 1) + 1 == g_exp[g]) ? 1 : 0;
            __syncthreads();
            if (sm_last) {
                __threadfence();
                int cnt = g_exp[g];
                float M2 = -3.0e38f;
                for (int pp = 0; pp < cnt; pp++) M2 = fmaxf(M2, g_pm[g * MAXP + pp]);
                float D2 = 0.f, R2 = 0.f;
                for (int pp = 0; pp < cnt; pp++) {
                    float f = __expf(g_pm[g * MAXP + pp] - M2);
                    D2 += g_pd[g * MAXP + pp] * f;
                    R2 += g_pr[(size_t)(g * MAXP + pp) * H + t] * f;
                }
                R2 = (D2 > 0.f) ? (R2 / D2) : 0.f;
                g_qstar[g * K2H + H + t] = R2;        // r half (q half written by lstm)
                if (t == 0) { g_cnt[g] = 0; g_done[g] = 0; }
            }
            __syncthreads();   // protect smem reuse for next sub-segment
            c0 = e;
        }
        if (e == segend) g++;
    }
}

__global__ __launch_bounds__(256, 4) void attn_p0(const float* __restrict__ x, int n, int chunk) {
    attn_body<0>(x, n, chunk);
}
__global__ __launch_bounds__(256, 4) void attn_p1(const float* __restrict__ x, int n, int chunk) {
    attn_body<1>(x, n, chunk);
}
__global__ __launch_bounds__(256, 4) void attn_p2(const float* __restrict__ x, int n, int chunk) {
    attn_body<2>(x, n, chunk);
}

// ---------------- tf32 tensor-core NT GEMM helpers ----------------
__device__ __forceinline__ unsigned f2tf(float f) {
    unsigned r; asm("cvt.rna.tf32.f32 %0, %1;" : "=r"(r) : "f"(f)); return r;
}
__device__ __forceinline__ void mma_tf32(float* d, const unsigned* a, const unsigned* b) {
    asm volatile("mma.sync.aligned.m16n8k8.row.col.f32.tf32.tf32.f32 "
        "{%0,%1,%2,%3}, {%4,%5,%6,%7}, {%8,%9}, {%0,%1,%2,%3};"
        : "+f"(d[0]), "+f"(d[1]), "+f"(d[2]), "+f"(d[3])
        : "r"(a[0]), "r"(a[1]), "r"(a[2]), "r"(a[3]), "r"(b[0]), "r"(b[1]));
}

// 64x64 output tile, 256 thr (8 warps 2Mx4N; warp tile 32x16), BK=32, double-buffered.
// smem layout: [row][40], k-chunk packed as 4 pairs {k, k+4} per 8-group with per-row
// rotation slot = (pair + row) & 3 -> all fragment loads are LDS.64, conflict-free.
__device__ __forceinline__ void gemm_mma64_body(const float* __restrict__ A,
                                                const float* __restrict__ Bm,
                                                float* __restrict__ C, int Ndim,
                                                int kbase, int nsteps) {
    __shared__ __align__(16) unsigned sA[2][64][40];
    __shared__ __align__(16) unsigned sB[2][64][40];
    int tid = threadIdx.x;
    int lane = tid & 31, warp = tid >> 5;
    int wm = (warp & 1) * 32, wn = (warp >> 1) * 16;
    int row0 = blockIdx.y * 64, col0 = blockIdx.x * 64;
    int lr = tid >> 2, kq = (tid & 3) * 8;   // staging row + k-group base
    int fr = lane >> 2, fc = lane & 3;
    int rot2 = ((fc + fr) & 3) * 2;          // shared pair slot for all frag rows

    const float* Apf = A + (size_t)(row0 + lr) * K2H + kbase + kq;
    const float* Bpf = Bm + (size_t)(col0 + lr) * K2H + kbase + kq;

    // stage chunk 0 into buffer 0
    {
        float4 a0 = *(const float4*)Apf;
        float4 a1 = *(const float4*)(Apf + 4);
        float4 b0 = *(const float4*)Bpf;
        float4 b1 = *(const float4*)(Bpf + 4);
        unsigned av[8] = { f2tf(a0.x), f2tf(a0.y), f2tf(a0.z), f2tf(a0.w),
                           f2tf(a1.x), f2tf(a1.y), f2tf(a1.z), f2tf(a1.w) };
        unsigned bv[8] = { f2tf(b0.x), f2tf(b0.y), f2tf(b0.z), f2tf(b0.w),
                           f2tf(b1.x), f2tf(b1.y), f2tf(b1.z), f2tf(b1.w) };
        #pragma unroll
        for (int p = 0; p < 4; p++) {
            int s = ((p + lr) & 3) * 2;
            *(uint2*)&sA[0][lr][kq + s] = make_uint2(av[p], av[p + 4]);
            *(uint2*)&sB[0][lr][kq + s] = make_uint2(bv[p], bv[p + 4]);
        }
    }
    __syncthreads();

    float acc[2][2][4] = {};
    float4 pa0, pa1, pb0, pb1;

    for (int s = 0; s < nsteps; s++) {
        int cur = s & 1, nxt = 1 - cur;
        if (s + 1 < nsteps) {   // global prefetch before the MMA burst
            int off = (s + 1) * 32;
            pa0 = *(const float4*)(Apf + off);
            pa1 = *(const float4*)(Apf + off + 4);
            pb0 = *(const float4*)(Bpf + off);
            pb1 = *(const float4*)(Bpf + off + 4);
        }

        #pragma unroll
        for (int ks = 0; ks < 4; ks++) {
            int so = ks * 8 + rot2;
            uint2 ua0 = *(const uint2*)&sA[cur][wm + fr][so];
            uint2 ua1 = *(const uint2*)&sA[cur][wm + fr + 8][so];
            uint2 ua2 = *(const uint2*)&sA[cur][wm + 16 + fr][so];
            uint2 ua3 = *(const uint2*)&sA[cur][wm + 24 + fr][so];
            uint2 ub0 = *(const uint2*)&sB[cur][wn + fr][so];
            uint2 ub1 = *(const uint2*)&sB[cur][wn + 8 + fr][so];
            unsigned a0[4] = { ua0.x, ua1.x, ua0.y, ua1.y };
            unsigned a1[4] = { ua2.x, ua3.x, ua2.y, ua3.y };
            unsigned b0[2] = { ub0.x, ub0.y };
            unsigned b1[2] = { ub1.x, ub1.y };
            mma_tf32(acc[0][0], a0, b0);
            mma_tf32(acc[0][1], a0, b1);
            mma_tf32(acc[1][0], a1, b0);
            mma_tf32(acc[1][1], a1, b1);
        }

        if (s + 1 < nsteps) {   // stage next chunk into the other buffer
            unsigned av[8] = { f2tf(pa0.x), f2tf(pa0.y), f2tf(pa0.z), f2tf(pa0.w),
                               f2tf(pa1.x), f2tf(pa1.y), f2tf(pa1.z), f2tf(pa1.w) };
            unsigned bv[8] = { f2tf(pb0.x), f2tf(pb0.y), f2tf(pb0.z), f2tf(pb0.w),
                               f2tf(pb1.x), f2tf(pb1.y), f2tf(pb1.z), f2tf(pb1.w) };
            #pragma unroll
            for (int p = 0; p < 4; p++) {
                int sl = ((p + lr) & 3) * 2;
                *(uint2*)&sA[nxt][lr][kq + sl] = make_uint2(av[p], av[p + 4]);
                *(uint2*)&sB[nxt][lr][kq + sl] = make_uint2(bv[p], bv[p + 4]);
            }
            __syncthreads();
        }
    }

    #pragma unroll
    for (int mm = 0; mm < 2; mm++)
    #pragma unroll
    for (int nn = 0; nn < 2; nn++) {
        int rr = row0 + wm + mm * 16 + fr;
        int cb = col0 + wn + nn * 8 + fc * 2;
        float2 v0 = { acc[mm][nn][0], acc[mm][nn][1] };
        float2 v1 = { acc[mm][nn][2], acc[mm][nn][3] };
        *(float2*)&C[(size_t)rr * Ndim + cb] = v0;
        *(float2*)&C[(size_t)(rr + 8) * Ndim + cb] = v1;
    }
}

__global__ __launch_bounds__(256) void gemm_gates() {
    // split-K=4: partial gates[z][512][1024] over K quarter z; grid (16, 8, 4) = 512 blocks
    int z = blockIdx.z;
    dep_sync();
    gemm_mma64_body(g_qstar, g_Wc, g_gates4 + (size_t)z * NB * G4, G4, z * 128, 4);
}

__global__ __launch_bounds__(256) void gemm_out(const float* __restrict__ W_out) {
    // split-K=4: partial out[z][512][256] over K quarter z; grid (4, 8, 4) = 128 blocks
    int z = blockIdx.z;
    dep_sync();
    gemm_mma64_body(g_qstar, W_out, g_out4 + (size_t)z * NB * H, H, z * 128, 4);
}

// ---------------- PDL launch helper ----------------
template <typename F, typename... Args>
static inline void pdl_launch(F* func, dim3 grid, dim3 block, Args... args) {
    cudaLaunchConfig_t cfg = {};
    cfg.gridDim = grid;
    cfg.blockDim = block;
    cfg.dynamicSmemBytes = 0;
    cfg.stream = 0;    // legacy default stream (same as <<<>>>)
    cudaLaunchAttribute at[1];
    at[0].id = cudaLaunchAttributeProgrammaticStreamSerialization;
    at[0].val.programmaticStreamSerializationAllowed = 1;
    cfg.attrs = at;
    cfg.numAttrs = 1;
    cudaLaunchKernelEx(&cfg, func, args...);
}

// ---------------- launcher ----------------
extern "C" void kernel_launch(void* const* d_in, const int* in_sizes, int n_in,
                              void* d_out, int out_size) {
    const float* x     = (const float*)d_in[0];
    const void*  batch = d_in[1];
    const float* W_ih  = (const float*)d_in[2];
    const float* W_hh  = (const float*)d_in[3];
    const float* b_ih  = (const float*)d_in[4];
    const float* b_hh  = (const float*)d_in[5];
    const float* W_out = (const float*)d_in[6];
    const float* b_out = (const float*)d_in[7];
    float* out = (float*)d_out;
    int n = in_sizes[0] / H;
    int chunk = (n + CHB - 1) / CHB;
    bool fit16 = (n <= MAXN);

    prep_kernel<<<(G4 * K2H / 4 + 255) / 256, 256>>>(W_ih, W_hh, b_ih, b_hh, batch, n);

    // step 1: gates = bias (q_star = hs = 0); pass 1 also fills the fp16 x cache
    pdl_launch(lstm_first, dim3(NB), dim3(256), chunk);
    pdl_launch(fit16 ? attn_p0 : attn_p2, dim3(CHB), dim3(256), x, n, chunk);

    // steps 2..3: passes 2-3 read fp16 x (half the bytes)
    for (int s = 1; s < 3; s++) {
        pdl_launch(gemm_gates, dim3(G4 / 64, NB / 64, 4), dim3(256));
        pdl_launch(lstm_step, dim3(NB), dim3(256));
        pdl_launch(fit16 ? attn_p1 : attn_p2, dim3(CHB), dim3(256), x, n, chunk);
    }

    pdl_launch(gemm_out, dim3(H / 64, NB / 64, 4), dim3(256), W_out);
    pdl_launch(out_epi, dim3(NB), dim3(256), b_out, out);
}

// round 17
// speedup vs baseline: 1.7649x; 1.0269x over previous
#include <cuda_runtime.h>
#include <cuda_fp16.h>
#include <math.h>

#define H      256
#define NB     512      // n_graphs
#define G4     1024     // 4*H
#define K2H    512      // 2*H
#define CHB    608      // attention chunk blocks (4 per SM x 152)
#define MAXP   8        // max partials per graph (<=3 actually occur)
#define MAXN   204800   // fp16 x-cache capacity (nodes)

// ---------------- device scratch (no allocation allowed) ----------------
__device__ __align__(16) float g_Wc[G4 * K2H];     // combined gate weight, tf32-rounded
__device__ __align__(16) float g_Wo[H * K2H];      // W_out copy, tf32-rounded
__device__ __align__(16) float g_bias[G4];         // b_ih + b_hh
__device__ __align__(16) float g_hs[NB * H];
__device__ __align__(16) float g_cs[NB * H];
__device__ __align__(16) float g_qstar[NB * K2H];  // [hs, r], tf32-rounded (feeds GEMMs only)
__device__ __align__(16) float g_gates4[4 * NB * G4]; // split-K=4 partial gates
__device__ __align__(16) float g_out4[4 * NB * H];    // split-K=4 partial out
__device__ __align__(16) __half g_x16[(size_t)MAXN * H]; // fp16 cache of x
__device__ int   g_seg[NB + 1];
__device__ int   g_cnt[NB];                        // partial slot counters
__device__ int   g_done[NB];                       // completed-partials counters
__device__ int   g_exp[NB];                        // expected partials per graph
__device__ float g_pm[NB * MAXP];                  // partial max
__device__ float g_pd[NB * MAXP];                  // partial denom (rel. to pm)
__device__ __align__(16) float g_pr[NB * MAXP * H];// partial weighted sum (rel. to pm)

__device__ __forceinline__ void dep_sync() {
#if __CUDA_ARCH__ >= 900
    cudaGridDependencySynchronize();
#endif
}

__device__ __forceinline__ unsigned f2tf(float f) {
    unsigned r; asm("cvt.rna.tf32.f32 %0, %1;" : "=r"(r) : "f"(f)); return r;
}
__device__ __forceinline__ float f2tff(float f) {
    unsigned r = f2tf(f); return __uint_as_float(r);
}

// ---------------- prep: Wcomb (tf32), Wo (tf32), bias, seg starts ----------------
__global__ void prep_kernel(const float* __restrict__ W_ih, const float* __restrict__ W_hh,
                            const float* __restrict__ b_ih, const float* __restrict__ b_hh,
                            const float* __restrict__ W_out,
                            const void* __restrict__ batch_raw, int n) {
    int i = blockIdx.x * blockDim.x + threadIdx.x;   // over G4*K2H/4 = 131072
    if (i < G4 * K2H / 4) {
        int j = i >> 7;              // row (gate index)
        int k4 = (i & 127) * 4;      // col (4-aligned)
        float4 v = *(const float4*)&W_ih[i * 4];
        if (k4 < H) {
            float4 w = *(const float4*)&W_hh[j * H + k4];
            v.x += w.x; v.y += w.y; v.z += w.z; v.w += w.w;
        }
        v.x = f2tff(v.x); v.y = f2tff(v.y); v.z = f2tff(v.z); v.w = f2tff(v.w);
        *(float4*)&g_Wc[i * 4] = v;
    }
    if (i < H * K2H / 4) {           // tf32-rounded copy of W_out
        float4 v = *(const float4*)&W_out[i * 4];
        v.x = f2tff(v.x); v.y = f2tff(v.y); v.z = f2tff(v.z); v.w = f2tff(v.w);
        *(float4*)&g_Wo[i * 4] = v;
    }
    if (i < G4) g_bias[i] = b_ih[i] + b_hh[i];
    if (i <= NB) {
        // lower_bound(i) over sorted batch; dtype-agnostic (int32 vs int64)
        const int* b32 = (const int*)batch_raw;
        bool is64 = (b32[n - 1] == 0);   // int64 view: high word of last elem (<512)
        int lo = 0, hi = n;
        if (is64) {
            const long long* b64 = (const long long*)batch_raw;
            long long gv = (long long)i;
            while (lo < hi) { int mid = (lo + hi) >> 1; if (b64[mid] < gv) lo = mid + 1; else hi = mid; }
        } else {
            while (lo < hi) { int mid = (lo + hi) >> 1; if (b32[mid] < i) lo = mid + 1; else hi = mid; }
        }
        g_seg[i] = lo;
    }
}

__device__ __forceinline__ float sigf(float v) { return 1.0f / (1.0f + __expf(-v)); }

// ---------------- LSTM step 1: q_star = hs = 0 -> gates = bias only ----------------
__global__ void lstm_first(int chunk) {
    dep_sync();
    int idx = blockIdx.x * blockDim.x + threadIdx.x;   // NB*H
    int g = idx >> 8;
    int t = idx & (H - 1);
    if (t == 0) {
        int s = g_seg[g], e = g_seg[g + 1];
        g_exp[g] = (e > s) ? ((e - 1) / chunk - s / chunk + 1) : 0;
    }
    float ig = g_bias[t], gg = g_bias[2 * H + t], og = g_bias[3 * H + t];
    float c = sigf(ig) * tanhf(gg);        // f-gate * cs(=0) drops out
    float h = sigf(og) * tanhf(c);
    g_cs[idx] = c;
    g_hs[idx] = h;
    g_qstar[g * K2H + t]     = f2tff(h);   // q half (tf32-rounded; GEMM-only consumer)
    g_qstar[g * K2H + H + t] = 0.f;        // r half (combine overwrites; stays 0 if empty graph)
}

// ---------------- LSTM steps 2..: sum split-K=4 gate partials + bias ----------------
__global__ void lstm_step() {
    dep_sync();
    int idx = blockIdx.x * blockDim.x + threadIdx.x;   // NB*H
    int g = idx >> 8;
    int t = idx & (H - 1);
    const float* gr0 = g_gates4 + g * G4;
    const float* gr1 = gr0 + NB * G4;
    const float* gr2 = gr1 + NB * G4;
    const float* gr3 = gr2 + NB * G4;
    float ig = gr0[t]         + gr1[t]         + gr2[t]         + gr3[t]         + g_bias[t];
    float fg = gr0[H + t]     + gr1[H + t]     + gr2[H + t]     + gr3[H + t]     + g_bias[H + t];
    float gg = gr0[2 * H + t] + gr1[2 * H + t] + gr2[2 * H + t] + gr3[2 * H + t] + g_bias[2 * H + t];
    float og = gr0[3 * H + t] + gr1[3 * H + t] + gr2[3 * H + t] + gr3[3 * H + t] + g_bias[3 * H + t];
    float c = sigf(fg) * g_cs[idx] + sigf(ig) * tanhf(gg);
    float h = sigf(og) * tanhf(c);
    g_cs[idx] = c;
    g_hs[idx] = h;
    g_qstar[g * K2H + t]     = f2tff(h);
    g_qstar[g * K2H + H + t] = 0.f;
}

// ---------------- out epilogue: sum 4 split-K partials + bias ----------------
__global__ void out_epi(const float* __restrict__ b_out, float* __restrict__ out) {
    dep_sync();
    int idx = blockIdx.x * blockDim.x + threadIdx.x;   // NB*H
    int t = idx & (H - 1);
    out[idx] = g_out4[idx] + g_out4[NB * H + idx]
             + g_out4[2 * NB * H + idx] + g_out4[3 * NB * H + idx] + b_out[t];
}

// ---------------- fp16 pack/unpack helpers ----------------
__device__ __forceinline__ uint4 f2h8(float4 a, float4 b) {
    uint4 h;
    __half2 t;
    t = __float22half2_rn(make_float2(a.x, a.y)); h.x = *(unsigned*)&t;
    t = __float22half2_rn(make_float2(a.z, a.w)); h.y = *(unsigned*)&t;
    t = __float22half2_rn(make_float2(b.x, b.y)); h.z = *(unsigned*)&t;
    t = __float22half2_rn(make_float2(b.z, b.w)); h.w = *(unsigned*)&t;
    return h;
}
__device__ __forceinline__ void h2f8(uint4 h, float4& a, float4& b) {
    float2 f;
    f = __half22float2(*(__half2*)&h.x); a.x = f.x; a.y = f.y;
    f = __half22float2(*(__half2*)&h.y); a.z = f.x; a.w = f.y;
    f = __half22float2(*(__half2*)&h.z); b.x = f.x; b.y = f.y;
    f = __half22float2(*(__half2*)&h.w); b.z = f.x; b.w = f.y;
}

// ---------------- balanced attention: equal node chunks -> partials; last block combines ----
// MODE 0: read fp32 x, also write fp16 cache. MODE 1: read fp16 cache. MODE 2: fp32 only.
template <int MODE>
__device__ __forceinline__ void attn_body(const float* __restrict__ x, int n, int chunk) {
    int c0 = blockIdx.x * chunk;
    if (c0 >= n) return;
    dep_sync();
    int c1 = min(n, c0 + chunk);
    int warp = threadIdx.x >> 5, lane = threadIdx.x & 31;
    int t = threadIdx.x;

    // find g with seg[g] <= c0 < seg[g+1] (max g with seg[g] <= c0)
    int lo = 0, hi = NB - 1;
    while (lo < hi) { int mid = (lo + hi + 1) >> 1; if (g_seg[mid] <= c0) lo = mid; else hi = mid - 1; }
    int g = lo;

    __shared__ float sm_m[8], sm_d[8];
    __shared__ float sm_r[8][H];
    __shared__ int sm_slot;
    __shared__ int sm_last;

    while (c0 < c1) {
        int segend = g_seg[g + 1];
        int e = min(segend, c1);
        if (e > c0) {
            const float4* qv = reinterpret_cast<const float4*>(g_hs + g * H);
            float4 q0 = qv[lane * 2];
            float4 q1 = qv[lane * 2 + 1];

            float m = -3.0e38f, d = 0.0f;
            float r0 = 0.f, r1 = 0.f, r2 = 0.f, r3 = 0.f, r4 = 0.f, r5 = 0.f, r6 = 0.f, r7 = 0.f;

            int i = c0 + warp * 2;
            for (; i + 1 < e; i += 16) {
                float4 a0, b0, a1, b1;
                if (MODE == 1) {
                    uint4 h0 = *((const uint4*)(g_x16 + (size_t)i * H) + lane);
                    uint4 h1 = *((const uint4*)(g_x16 + (size_t)(i + 1) * H) + lane);
                    h2f8(h0, a0, b0);
                    h2f8(h1, a1, b1);
                } else {
                    const float4* xv0 = reinterpret_cast<const float4*>(x + (size_t)i * H);
                    const float4* xv1 = reinterpret_cast<const float4*>(x + (size_t)(i + 1) * H);
                    a0 = xv0[lane * 2];
                    b0 = xv0[lane * 2 + 1];
                    a1 = xv1[lane * 2];
                    b1 = xv1[lane * 2 + 1];
                    if (MODE == 0) {
                        *((uint4*)(g_x16 + (size_t)i * H) + lane)       = f2h8(a0, b0);
                        *((uint4*)(g_x16 + (size_t)(i + 1) * H) + lane) = f2h8(a1, b1);
                    }
                }

                float p0 = a0.x * q0.x + a0.y * q0.y + a0.z * q0.z + a0.w * q0.w
                         + b0.x * q1.x + b0.y * q1.y + b0.z * q1.z + b0.w * q1.w;
                float p1 = a1.x * q0.x + a1.y * q0.y + a1.z * q0.z + a1.w * q0.w
                         + b1.x * q1.x + b1.y * q1.y + b1.z * q1.z + b1.w * q1.w;
                #pragma unroll
                for (int o = 16; o > 0; o >>= 1) {
                    p0 += __shfl_xor_sync(0xffffffffu, p0, o);
                    p1 += __shfl_xor_sync(0xffffffffu, p1, o);
                }
                if (p0 > m) {
                    float f = __expf(m - p0);
                    d *= f; r0 *= f; r1 *= f; r2 *= f; r3 *= f; r4 *= f; r5 *= f; r6 *= f; r7 *= f;
                    m = p0;
                }
                float w = __expf(p0 - m);
                d += w;
                r0 = fmaf(w, a0.x, r0); r1 = fmaf(w, a0.y, r1);
                r2 = fmaf(w, a0.z, r2); r3 = fmaf(w, a0.w, r3);
                r4 = fmaf(w, b0.x, r4); r5 = fmaf(w, b0.y, r5);
                r6 = fmaf(w, b0.z, r6); r7 = fmaf(w, b0.w, r7);
                if (p1 > m) {
                    float f = __expf(m - p1);
                    d *= f; r0 *= f; r1 *= f; r2 *= f; r3 *= f; r4 *= f; r5 *= f; r6 *= f; r7 *= f;
                    m = p1;
                }
                w = __expf(p1 - m);
                d += w;
                r0 = fmaf(w, a1.x, r0); r1 = fmaf(w, a1.y, r1);
                r2 = fmaf(w, a1.z, r2); r3 = fmaf(w, a1.w, r3);
                r4 = fmaf(w, b1.x, r4); r5 = fmaf(w, b1.y, r5);
                r6 = fmaf(w, b1.z, r6); r7 = fmaf(w, b1.w, r7);
            }
            if (i < e) {
                float4 a0, b0;
                if (MODE == 1) {
                    uint4 h0 = *((const uint4*)(g_x16 + (size_t)i * H) + lane);
                    h2f8(h0, a0, b0);
                } else {
                    const float4* xv0 = reinterpret_cast<const float4*>(x + (size_t)i * H);
                    a0 = xv0[lane * 2];
                    b0 = xv0[lane * 2 + 1];
                    if (MODE == 0)
                        *((uint4*)(g_x16 + (size_t)i * H) + lane) = f2h8(a0, b0);
                }
                float p0 = a0.x * q0.x + a0.y * q0.y + a0.z * q0.z + a0.w * q0.w
                         + b0.x * q1.x + b0.y * q1.y + b0.z * q1.z + b0.w * q1.w;
                #pragma unroll
                for (int o = 16; o > 0; o >>= 1) p0 += __shfl_xor_sync(0xffffffffu, p0, o);
                if (p0 > m) {
                    float f = __expf(m - p0);
                    d *= f; r0 *= f; r1 *= f; r2 *= f; r3 *= f; r4 *= f; r5 *= f; r6 *= f; r7 *= f;
                    m = p0;
                }
                float w = __expf(p0 - m);
                d += w;
                r0 = fmaf(w, a0.x, r0); r1 = fmaf(w, a0.y, r1);
                r2 = fmaf(w, a0.z, r2); r3 = fmaf(w, a0.w, r3);
                r4 = fmaf(w, b0.x, r4); r5 = fmaf(w, b0.y, r5);
                r6 = fmaf(w, b0.z, r6); r7 = fmaf(w, b0.w, r7);
            }

            // block-level merge of 8 warps
            if (lane == 0) { sm_m[warp] = m; sm_d[warp] = d; }
            __syncthreads();
            float M = sm_m[0];
            #pragma unroll
            for (int w = 1; w < 8; w++) M = fmaxf(M, sm_m[w]);
            float D = 0.f;
            #pragma unroll
            for (int w = 0; w < 8; w++) D += sm_d[w] * __expf(sm_m[w] - M);

            float sc = __expf(m - M);   // 0 for warps with no nodes
            int base = lane * 8;
            sm_r[warp][base + 0] = r0 * sc; sm_r[warp][base + 1] = r1 * sc;
            sm_r[warp][base + 2] = r2 * sc; sm_r[warp][base + 3] = r3 * sc;
            sm_r[warp][base + 4] = r4 * sc; sm_r[warp][base + 5] = r5 * sc;
            sm_r[warp][base + 6] = r6 * sc; sm_r[warp][base + 7] = r7 * sc;
            if (t == 0) sm_slot = atomicAdd(&g_cnt[g], 1);
            __syncthreads();

            float R = 0.f;
            #pragma unroll
            for (int w = 0; w < 8; w++) R += sm_r[w][t];
            int p = g * MAXP + sm_slot;
            g_pr[(size_t)p * H + t] = R;              // unnormalized, relative to M
            if (t == 0) { g_pm[p] = M; g_pd[p] = D; }

            // last-block-done combine
            __threadfence();
            __syncthreads();
            if (t == 0) sm_last = (atomicAdd(&g_done[g], 1) + 1 == g_exp[g]) ? 1 : 0;
            __syncthreads();
            if (sm_last) {
                __threadfence();
                int cnt = g_exp[g];
                float M2 = -3.0e38f;
                for (int pp = 0; pp < cnt; pp++) M2 = fmaxf(M2, g_pm[g * MAXP + pp]);
                float D2 = 0.f, R2 = 0.f;
                for (int pp = 0; pp < cnt; pp++) {
                    float f = __expf(g_pm[g * MAXP + pp] - M2);
                    D2 += g_pd[g * MAXP + pp] * f;
                    R2 += g_pr[(size_t)(g * MAXP + pp) * H + t] * f;
                }
                R2 = (D2 > 0.f) ? (R2 / D2) : 0.f;
                g_qstar[g * K2H + H + t] = f2tff(R2); // r half, tf32-rounded (GEMM-only consumer)
                if (t == 0) { g_cnt[g] = 0; g_done[g] = 0; }
            }
            __syncthreads();   // protect smem reuse for next sub-segment
            c0 = e;
        }
        if (e == segend) g++;
    }
}

__global__ __launch_bounds__(256, 4) void attn_p0(const float* __restrict__ x, int n, int chunk) {
    attn_body<0>(x, n, chunk);
}
__global__ __launch_bounds__(256, 4) void attn_p1(const float* __restrict__ x, int n, int chunk) {
    attn_body<1>(x, n, chunk);
}
__global__ __launch_bounds__(256, 4) void attn_p2(const float* __restrict__ x, int n, int chunk) {
    attn_body<2>(x, n, chunk);
}

// ---------------- tf32 tensor-core NT GEMM (inputs pre-rounded; cp.async staging) ----------------
__device__ __forceinline__ void mma_tf32(float* d, const unsigned* a, const unsigned* b) {
    asm volatile("mma.sync.aligned.m16n8k8.row.col.f32.tf32.tf32.f32 "
        "{%0,%1,%2,%3}, {%4,%5,%6,%7}, {%8,%9}, {%0,%1,%2,%3};"
        : "+f"(d[0]), "+f"(d[1]), "+f"(d[2]), "+f"(d[3])
        : "r"(a[0]), "r"(a[1]), "r"(a[2]), "r"(a[3]), "r"(b[0]), "r"(b[1]));
}
__device__ __forceinline__ void cpa16(unsigned dst, const float* src) {
    asm volatile("cp.async.cg.shared.global [%0], [%1], 16;" :: "r"(dst), "l"(src));
}

// 64x64 output tile, 256 thr (8 warps 2Mx4N; warp tile 32x16), BK=32,
// cp.async double-buffered. Partial C (no bias) over [kbase, kbase+nsteps*32).
// A and Bm must be pre-rounded to tf32 values (stored as float bits).
__device__ __forceinline__ void gemm_mma64_body(const float* __restrict__ A,
                                                const float* __restrict__ Bm,
                                                float* __restrict__ C, int Ndim,
                                                int kbase, int nsteps) {
    __shared__ __align__(16) unsigned sA[2][64][36];   // row stride 144B (16B-aligned)
    __shared__ __align__(16) unsigned sB[2][64][36];
    int tid = threadIdx.x;
    int lane = tid & 31, warp = tid >> 5;
    int wm = (warp & 1) * 32, wn = (warp >> 1) * 16;
    int row0 = blockIdx.y * 64, col0 = blockIdx.x * 64;
    int lr = tid >> 2, kq = (tid & 3) * 8;
    int fr = lane >> 2, fc = lane & 3;

    const float* Apf = A + (size_t)(row0 + lr) * K2H + kbase + kq;
    const float* Bpf = Bm + (size_t)(col0 + lr) * K2H + kbase + kq;
    unsigned saw = (unsigned)__cvta_generic_to_shared(&sA[0][lr][kq]);
    unsigned sbw = (unsigned)__cvta_generic_to_shared(&sB[0][lr][kq]);
    const unsigned bstr = 64 * 36 * 4;   // bytes per buffer

    // stage chunk 0 into buffer 0
    cpa16(saw, Apf);      cpa16(saw + 16, Apf + 4);
    cpa16(sbw, Bpf);      cpa16(sbw + 16, Bpf + 4);
    asm volatile("cp.async.commit_group;");

    float acc[2][2][4] = {};

    for (int s = 0; s < nsteps; s++) {
        int cur = s & 1, nxt = 1 - cur;
        if (s + 1 < nsteps) {   // stage next chunk into the other buffer (async)
            int off = (s + 1) * 32;
            unsigned da = saw + nxt * bstr, db = sbw + nxt * bstr;
            cpa16(da, Apf + off);      cpa16(da + 16, Apf + off + 4);
            cpa16(db, Bpf + off);      cpa16(db + 16, Bpf + off + 4);
            asm volatile("cp.async.commit_group;");
            asm volatile("cp.async.wait_group 1;");   // chunk s landed
        } else {
            asm volatile("cp.async.wait_group 0;");
        }
        __syncthreads();

        #pragma unroll
        for (int ks = 0; ks < 4; ks++) {
            int kc = ks * 8 + fc;
            unsigned a0[4] = { sA[cur][wm + fr][kc],      sA[cur][wm + fr + 8][kc],
                               sA[cur][wm + fr][kc + 4],  sA[cur][wm + fr + 8][kc + 4] };
            unsigned a1[4] = { sA[cur][wm + 16 + fr][kc],     sA[cur][wm + 24 + fr][kc],
                               sA[cur][wm + 16 + fr][kc + 4], sA[cur][wm + 24 + fr][kc + 4] };
            unsigned b0[2] = { sB[cur][wn + fr][kc], sB[cur][wn + fr][kc + 4] };
            unsigned b1[2] = { sB[cur][wn + 8 + fr][kc], sB[cur][wn + 8 + fr][kc + 4] };
            mma_tf32(acc[0][0], a0, b0);
            mma_tf32(acc[0][1], a0, b1);
            mma_tf32(acc[1][0], a1, b0);
            mma_tf32(acc[1][1], a1, b1);
        }
        __syncthreads();   // protect cur buffer before restaging
    }

    #pragma unroll
    for (int mm = 0; mm < 2; mm++)
    #pragma unroll
    for (int nn = 0; nn < 2; nn++) {
        int rr = row0 + wm + mm * 16 + fr;
        int cb = col0 + wn + nn * 8 + fc * 2;
        float2 v0 = { acc[mm][nn][0], acc[mm][nn][1] };
        float2 v1 = { acc[mm][nn][2], acc[mm][nn][3] };
        *(float2*)&C[(size_t)rr * Ndim + cb] = v0;
        *(float2*)&C[(size_t)(rr + 8) * Ndim + cb] = v1;
    }
}

__global__ __launch_bounds__(256) void gemm_gates() {
    // split-K=4: partial gates[z][512][1024] over K quarter z; grid (16, 8, 4) = 512 blocks
    int z = blockIdx.z;
    dep_sync();
    gemm_mma64_body(g_qstar, g_Wc, g_gates4 + (size_t)z * NB * G4, G4, z * 128, 4);
}

__global__ __launch_bounds__(256) void gemm_out() {
    // split-K=4: partial out[z][512][256] over K quarter z; grid (4, 8, 4) = 128 blocks
    int z = blockIdx.z;
    dep_sync();
    gemm_mma64_body(g_qstar, g_Wo, g_out4 + (size_t)z * NB * H, H, z * 128, 4);
}

// ---------------- PDL launch helper ----------------
template <typename F, typename... Args>
static inline void pdl_launch(F* func, dim3 grid, dim3 block, Args... args) {
    cudaLaunchConfig_t cfg = {};
    cfg.gridDim = grid;
    cfg.blockDim = block;
    cfg.dynamicSmemBytes = 0;
    cfg.stream = 0;    // legacy default stream (same as <<<>>>)
    cudaLaunchAttribute at[1];
    at[0].id = cudaLaunchAttributeProgrammaticStreamSerialization;
    at[0].val.programmaticStreamSerializationAllowed = 1;
    cfg.attrs = at;
    cfg.numAttrs = 1;
    cudaLaunchKernelEx(&cfg, func, args...);
}

// ---------------- launcher ----------------
extern "C" void kernel_launch(void* const* d_in, const int* in_sizes, int n_in,
                              void* d_out, int out_size) {
    const float* x     = (const float*)d_in[0];
    const void*  batch = d_in[1];
    const float* W_ih  = (const float*)d_in[2];
    const float* W_hh  = (const float*)d_in[3];
    const float* b_ih  = (const float*)d_in[4];
    const float* b_hh  = (const float*)d_in[5];
    const float* W_out = (const float*)d_in[6];
    const float* b_out = (const float*)d_in[7];
    float* out = (float*)d_out;
    int n = in_sizes[0] / H;
    int chunk = (n + CHB - 1) / CHB;
    bool fit16 = (n <= MAXN);

    prep_kernel<<<(G4 * K2H / 4 + 255) / 256, 256>>>(W_ih, W_hh, b_ih, b_hh, W_out, batch, n);

    // step 1: gates = bias (q_star = hs = 0); pass 1 also fills the fp16 x cache
    pdl_launch(lstm_first, dim3(NB), dim3(256), chunk);
    pdl_launch(fit16 ? attn_p0 : attn_p2, dim3(CHB), dim3(256), x, n, chunk);

    // steps 2..3: passes 2-3 read fp16 x (half the bytes)
    for (int s = 1; s < 3; s++) {
        pdl_launch(gemm_gates, dim3(G4 / 64, NB / 64, 4), dim3(256));
        pdl_launch(lstm_step, dim3(NB), dim3(256));
        pdl_launch(fit16 ? attn_p1 : attn_p2, dim3(CHB), dim3(256), x, n, chunk);
    }

    pdl_launch(gemm_out, dim3(H / 64, NB / 64, 4), dim3(256));
    pdl_launch(out_epi, dim3(NB), dim3(256), b_out, out);
}